// round 5
// baseline (speedup 1.0000x reference)
#include <cuda_runtime.h>
#include <cuda_bf16.h>
#include <cuda_fp16.h>
#include <math.h>

// ---------------- static config ----------------
#define B_    4
#define BC_   256
#define PC_   64
#define HC_   256
#define H_    200
#define W_    400
#define P_    10
#define Hg_   20
#define Wg_   40
#define LQ_   800
#define MT_   (B_*LQ_)     // 3200 rows
#define NH_   8
#define NP_   8
#define DH_   32
#define MLPD_ 1024
#define NEXP_ 25600
#define KBEV_ 25600
#define KPR_  6400

// ---------------- scratch ----------------
__device__ float g_tgt [MT_*HC_];
__device__ float g_pr  [MT_*HC_];
__device__ float g_t   [MT_*HC_];
__device__ float g_s   [MT_*HC_];
__device__ float g_val [MT_*HC_];
__device__ float g_attn[MT_*HC_];
__device__ float g_off [MT_*NH_*NP_*2];
__device__ float g_aw  [MT_*NH_*NP_];
__device__ float g_part[4*MT_*HC_];
__device__ __half g_exph[(size_t)MT_*NEXP_];    // 164MB fp16 expand temp

// bf16 hi/lo planes
__device__ __align__(256) __nv_bfloat16 g_imh [(size_t)MT_*KBEV_];
__device__ __align__(256) __nv_bfloat16 g_iml [(size_t)MT_*KBEV_];
__device__ __align__(256) __nv_bfloat16 g_wh  [6553600];
__device__ __align__(256) __nv_bfloat16 g_wl  [6553600];
__device__ __align__(256) __nv_bfloat16 g_fc1h[2*MLPD_*HC_];
__device__ __align__(256) __nv_bfloat16 g_fc1l[2*MLPD_*HC_];
__device__ __align__(256) __nv_bfloat16 g_fc2h[2*HC_*MLPD_];
__device__ __align__(256) __nv_bfloat16 g_fc2l[2*HC_*MLPD_];
__device__ __align__(256) __nv_bfloat16 g_vph [2*HC_*HC_];
__device__ __align__(256) __nv_bfloat16 g_vpl [2*HC_*HC_];
__device__ __align__(256) __nv_bfloat16 g_oph [2*HC_*HC_];
__device__ __align__(256) __nv_bfloat16 g_opl [2*HC_*HC_];
__device__ __align__(256) __nv_bfloat16 g_ofh [2*128*HC_];
__device__ __align__(256) __nv_bfloat16 g_ofl [2*128*HC_];
__device__ __align__(256) __nv_bfloat16 g_th  [MT_*HC_];
__device__ __align__(256) __nv_bfloat16 g_tl  [MT_*HC_];
__device__ __align__(256) __nv_bfloat16 g_sh  [MT_*HC_];
__device__ __align__(256) __nv_bfloat16 g_sl  [MT_*HC_];
__device__ __align__(256) __nv_bfloat16 g_ath [MT_*HC_];
__device__ __align__(256) __nv_bfloat16 g_atl [MT_*HC_];
__device__ __align__(256) __nv_bfloat16 g_mlph[MT_*MLPD_];
__device__ __align__(256) __nv_bfloat16 g_mlpl[MT_*MLPD_];
__device__ __align__(256) __nv_bfloat16 g_tgh [MT_*HC_];
__device__ __align__(256) __nv_bfloat16 g_tgl [MT_*HC_];

// ---------------- helpers ----------------
__device__ __forceinline__ float gelu_exact(float x) {
    return 0.5f * x * (1.0f + erff(x * 0.70710678118654752f));
}
__device__ __forceinline__ void cvt_split2(float x, float y, unsigned &hi, unsigned &lo) {
    __nv_bfloat16 hx = __float2bfloat16(x);
    __nv_bfloat16 hy = __float2bfloat16(y);
    float rx = x - __bfloat162float(hx);
    float ry = y - __bfloat162float(hy);
    __nv_bfloat16 lx = __float2bfloat16(rx);
    __nv_bfloat16 ly = __float2bfloat16(ry);
    hi = ((unsigned)__bfloat16_as_ushort(hy) << 16) | (unsigned)__bfloat16_as_ushort(hx);
    lo = ((unsigned)__bfloat16_as_ushort(ly) << 16) | (unsigned)__bfloat16_as_ushort(lx);
}
__device__ __forceinline__ void split1(float v, __nv_bfloat16 &h, __nv_bfloat16 &l) {
    h = __float2bfloat16(v);
    l = __float2bfloat16(v - __bfloat162float(h));
}
__device__ __forceinline__ void mma_bf16(float* c,
                                         unsigned a0, unsigned a1, unsigned a2, unsigned a3,
                                         unsigned b0, unsigned b1) {
    asm volatile(
        "mma.sync.aligned.m16n8k16.row.col.f32.bf16.bf16.f32 "
        "{%0,%1,%2,%3}, {%4,%5,%6,%7}, {%8,%9}, {%0,%1,%2,%3};\n"
        : "+f"(c[0]), "+f"(c[1]), "+f"(c[2]), "+f"(c[3])
        : "r"(a0), "r"(a1), "r"(a2), "r"(a3), "r"(b0), "r"(b1));
}
__device__ __forceinline__ unsigned smem_u32(const void* p) {
    return (unsigned)__cvta_generic_to_shared(p);
}
__device__ __forceinline__ void cp16(unsigned s, const void* g) {
    asm volatile("cp.async.cg.shared.global [%0], [%1], 16;" :: "r"(s), "l"(g));
}
__device__ __forceinline__ void cp_commit() { asm volatile("cp.async.commit_group;"); }
template<int NN> __device__ __forceinline__ void cp_wait() {
    asm volatile("cp.async.wait_group %0;" :: "n"(NN));
}
__device__ __forceinline__ void ldsm4(unsigned &r0, unsigned &r1, unsigned &r2, unsigned &r3,
                                      unsigned addr) {
    asm volatile("ldmatrix.sync.aligned.m8n8.x4.shared.b16 {%0,%1,%2,%3}, [%4];"
                 : "=r"(r0), "=r"(r1), "=r"(r2), "=r"(r3) : "r"(addr));
}

// ==========================================================================
// fp32 -> bf16 hi/lo planes
// ==========================================================================
__global__ void convert_pair_k(const float* __restrict__ X,
                               __nv_bfloat16* __restrict__ Ph,
                               __nv_bfloat16* __restrict__ Pl, int n4) {
    for (int i = blockIdx.x * blockDim.x + threadIdx.x; i < n4; i += gridDim.x * blockDim.x) {
        float4 v = ((const float4*)X)[i];
        unsigned h0, l0, h1, l1;
        cvt_split2(v.x, v.y, h0, l0);
        cvt_split2(v.z, v.w, h1, l1);
        ((uint2*)Ph)[i] = make_uint2(h0, h1);
        ((uint2*)Pl)[i] = make_uint2(l0, l1);
    }
}

// ==========================================================================
// im2col + split to bf16 planes
// ==========================================================================
template<int CIN>
__global__ void im2col_pair_k(const float* __restrict__ X,
                              __nv_bfloat16* __restrict__ Ph,
                              __nv_bfloat16* __restrict__ Pl) {
    __shared__ float s[4000];
    int hg = blockIdx.x, ci = blockIdx.y, b = blockIdx.z;
    int tid = threadIdx.x;
    const int K = CIN * 100;
    const float* src = X + ((size_t)(b * CIN + ci) * H_ + hg * P_) * W_;
    for (int i = tid; i < 4000; i += 256) s[i] = src[i];
    __syncthreads();
    size_t rowbase = (size_t)(b * LQ_ + hg * Wg_);
    for (int j = tid; j < 4000; j += 256) {
        int wg = j / 100, idx = j - wg * 100;
        int py = idx / 10, px = idx - py * 10;
        float v = s[py * 400 + wg * 10 + px];
        __nv_bfloat16 h, l; split1(v, h, l);
        size_t o = (rowbase + wg) * K + ci * 100 + idx;
        Ph[o] = h; Pl[o] = l;
    }
}

// ==========================================================================
// Fast GEMM, 128x128x32, bf16 hi/lo planes, flexible epilogue via flags.
// ==========================================================================
#define FB_BIAS 1u
#define FB_GELU 2u
#define FB_RES  4u
#define FB_PAIR 8u
#define FB_F32  16u
#define FB_HALF 32u
#define GSTG 40960

template<unsigned MODE, int SPLIT>
__global__ void __launch_bounds__(256) gbf_k(
        const __nv_bfloat16* __restrict__ Ah_g, const __nv_bfloat16* __restrict__ Al_g,
        const __nv_bfloat16* __restrict__ Bh_g, const __nv_bfloat16* __restrict__ Bl_g,
        const float* __restrict__ bias, const float* __restrict__ R,
        float* __restrict__ C, __half* __restrict__ Ch,
        __nv_bfloat16* __restrict__ Ph, __nv_bfloat16* __restrict__ Pl,
        int N, int K) {
    extern __shared__ char smraw[];
    unsigned sbase = smem_u32(smraw);

    int tid = threadIdx.x, warp = tid >> 5, lane = tid & 31;
    int m0 = blockIdx.y * 128, n0 = blockIdx.x * 128;
    int Kc = K / SPLIT;
    int kstart = (SPLIT > 1) ? blockIdx.z * Kc : 0;
    int nk = Kc / 32;
    int wm = (warp >> 2) * 64, wn = (warp & 3) * 32;
    int gid = lane >> 2, tig = lane & 3;

    float acc[4][4][4];
#pragma unroll
    for (int mi = 0; mi < 4; mi++)
#pragma unroll
        for (int ni = 0; ni < 4; ni++)
#pragma unroll
            for (int q = 0; q < 4; q++) acc[mi][ni][q] = 0.f;

    auto load_tile = [&](int kt, int st) {
        int kb = kstart + kt * 32;
        unsigned sb = sbase + st * GSTG;
#pragma unroll
        for (int j = 0; j < 2; j++) {
            int c = j * 256 + tid;
            int row = c >> 2, q = c & 3;
            unsigned so = row * 80 + q * 16;
            size_t ga = (size_t)(m0 + row) * K + kb + q * 8;
            size_t gb = (size_t)(n0 + row) * K + kb + q * 8;
            cp16(sb +         so, Ah_g + ga);
            cp16(sb + 10240 + so, Al_g + ga);
            cp16(sb + 20480 + so, Bh_g + gb);
            cp16(sb + 30720 + so, Bl_g + gb);
        }
    };

    auto compute = [&](int st) {
        unsigned sb = sbase + st * GSTG;
#pragma unroll
        for (int s = 0; s < 2; s++) {
            unsigned ah[4][4], al[4][4], bh[4][2], bl[4][2];
            int arow = wm + (lane & 15);
            unsigned abyte = ((lane >> 4) * 16) + s * 32;
#pragma unroll
            for (int mi = 0; mi < 4; mi++) {
                unsigned ad = sb + (arow + mi * 16) * 80 + abyte;
                ldsm4(ah[mi][0], ah[mi][1], ah[mi][2], ah[mi][3], ad);
                ldsm4(al[mi][0], al[mi][1], al[mi][2], al[mi][3], ad + 10240);
            }
            int q = lane >> 3, r = lane & 7;
            int brow = wn + ((q >> 1) << 3) + r;
            unsigned bbyte = (q & 1) * 16 + s * 32;
#pragma unroll
            for (int nj = 0; nj < 2; nj++) {
                unsigned bd = sb + 20480 + (brow + nj * 16) * 80 + bbyte;
                unsigned r0, r1, r2, r3;
                ldsm4(r0, r1, r2, r3, bd);
                bh[nj*2][0] = r0; bh[nj*2][1] = r1; bh[nj*2+1][0] = r2; bh[nj*2+1][1] = r3;
                ldsm4(r0, r1, r2, r3, bd + 10240);
                bl[nj*2][0] = r0; bl[nj*2][1] = r1; bl[nj*2+1][0] = r2; bl[nj*2+1][1] = r3;
            }
#pragma unroll
            for (int mi = 0; mi < 4; mi++)
#pragma unroll
                for (int ni = 0; ni < 4; ni++) {
                    mma_bf16(acc[mi][ni], ah[mi][0], ah[mi][1], ah[mi][2], ah[mi][3],
                             bh[ni][0], bh[ni][1]);
                    mma_bf16(acc[mi][ni], ah[mi][0], ah[mi][1], ah[mi][2], ah[mi][3],
                             bl[ni][0], bl[ni][1]);
                    mma_bf16(acc[mi][ni], al[mi][0], al[mi][1], al[mi][2], al[mi][3],
                             bh[ni][0], bh[ni][1]);
                }
        }
    };

    load_tile(0, 0);
    cp_commit();
    for (int kt = 0; kt < nk; kt++) {
        if (kt + 1 < nk) {
            load_tile(kt + 1, (kt + 1) & 1);
            cp_commit();
            cp_wait<1>();
        } else {
            cp_wait<0>();
        }
        __syncthreads();
        compute(kt & 1);
        __syncthreads();
    }

#pragma unroll
    for (int mi = 0; mi < 4; mi++) {
#pragma unroll
        for (int ni = 0; ni < 4; ni++) {
            int m = m0 + wm + mi * 16 + gid;
            int n = n0 + wn + ni * 8 + tig * 2;
            float v0 = acc[mi][ni][0], v1 = acc[mi][ni][1];
            float v2 = acc[mi][ni][2], v3 = acc[mi][ni][3];
            if (SPLIT > 1) {
                float* Cp = C + (size_t)blockIdx.z * ((size_t)MT_ * N);
                Cp[(size_t)m * N + n] = v0;       Cp[(size_t)m * N + n + 1] = v1;
                Cp[(size_t)(m + 8) * N + n] = v2; Cp[(size_t)(m + 8) * N + n + 1] = v3;
            } else {
                if (MODE & FB_BIAS) {
                    float b0 = bias[n], b1 = bias[n + 1];
                    v0 += b0; v1 += b1; v2 += b0; v3 += b1;
                }
                if (MODE & FB_RES) {
                    const float* rp = R + (size_t)m * N + n;
                    v0 += rp[0]; v1 += rp[1];
                    v2 += rp[(size_t)8 * N]; v3 += rp[(size_t)8 * N + 1];
                }
                if (MODE & FB_GELU) {
                    v0 = gelu_exact(v0); v1 = gelu_exact(v1);
                    v2 = gelu_exact(v2); v3 = gelu_exact(v3);
                }
                size_t o0 = (size_t)m * N + n, o1 = (size_t)(m + 8) * N + n;
                if (MODE & FB_F32) {
                    C[o0] = v0; C[o0 + 1] = v1; C[o1] = v2; C[o1 + 1] = v3;
                }
                if (MODE & FB_HALF) {
                    Ch[o0] = __float2half(v0); Ch[o0 + 1] = __float2half(v1);
                    Ch[o1] = __float2half(v2); Ch[o1 + 1] = __float2half(v3);
                }
                if (MODE & FB_PAIR) {
                    __nv_bfloat16 h, l;
                    split1(v0, h, l); Ph[o0] = h;     Pl[o0] = l;
                    split1(v1, h, l); Ph[o0 + 1] = h; Pl[o0 + 1] = l;
                    split1(v2, h, l); Ph[o1] = h;     Pl[o1] = l;
                    split1(v3, h, l); Ph[o1 + 1] = h; Pl[o1 + 1] = l;
                }
            }
        }
    }
}

// ==========================================================================
// Slow-path NT GEMM (only for tiny aw: N=64)
// ==========================================================================
#define SSTR 20
__global__ __launch_bounds__(128) void mma_gemm_aw_k(
        const float* __restrict__ A, const float* __restrict__ Wt,
        const float* __restrict__ bias, float* __restrict__ C, int N, int K) {
    __shared__ unsigned Ah[64*SSTR], Al[64*SSTR], Bh[64*SSTR], Bl[64*SSTR];
    int tid  = threadIdx.x;
    int warp = tid >> 5, lane = tid & 31;
    int gid  = lane >> 2, tig = lane & 3;
    int m0 = blockIdx.y * 64, n0 = blockIdx.x * 64;
    int wm = (warp & 1) * 32, wn = (warp >> 1) * 32;

    int row = tid >> 1, half = tid & 1;
    const float* ap = A  + (size_t)(m0 + row) * K + half * 16;
    const float* bp = Wt + (size_t)(n0 + row) * K + half * 16;

    float4 fa[4], fb[4];
#pragma unroll
    for (int i = 0; i < 4; i++) {
        fa[i] = *(const float4*)(ap + i * 4);
        fb[i] = *(const float4*)(bp + i * 4);
    }
    float acc[2][4][4];
#pragma unroll
    for (int mi = 0; mi < 2; mi++)
#pragma unroll
        for (int ni = 0; ni < 4; ni++)
#pragma unroll
            for (int q = 0; q < 4; q++) acc[mi][ni][q] = 0.f;

    for (int k0 = 0; k0 < K; k0 += 32) {
        int sb = row * SSTR + half * 8;
#pragma unroll
        for (int i = 0; i < 4; i++) {
            unsigned h0, l0, h1, l1;
            cvt_split2(fa[i].x, fa[i].y, h0, l0);
            cvt_split2(fa[i].z, fa[i].w, h1, l1);
            Ah[sb + i*2] = h0; Ah[sb + i*2 + 1] = h1;
            Al[sb + i*2] = l0; Al[sb + i*2 + 1] = l1;
            cvt_split2(fb[i].x, fb[i].y, h0, l0);
            cvt_split2(fb[i].z, fb[i].w, h1, l1);
            Bh[sb + i*2] = h0; Bh[sb + i*2 + 1] = h1;
            Bl[sb + i*2] = l0; Bl[sb + i*2 + 1] = l1;
        }
        __syncthreads();
        if (k0 + 32 < K) {
#pragma unroll
            for (int i = 0; i < 4; i++) {
                fa[i] = *(const float4*)(ap + k0 + 32 + i * 4);
                fb[i] = *(const float4*)(bp + k0 + 32 + i * 4);
            }
        }
#pragma unroll
        for (int s = 0; s < 2; s++) {
            unsigned ah[2][4], al[2][4], bh[4][2], bl[4][2];
            int p = s * 8 + tig;
#pragma unroll
            for (int mi = 0; mi < 2; mi++) {
                int r0 = (wm + mi * 16 + gid) * SSTR;
                int r8 = r0 + 8 * SSTR;
                ah[mi][0] = Ah[r0 + p];     ah[mi][1] = Ah[r8 + p];
                ah[mi][2] = Ah[r0 + p + 4]; ah[mi][3] = Ah[r8 + p + 4];
                al[mi][0] = Al[r0 + p];     al[mi][1] = Al[r8 + p];
                al[mi][2] = Al[r0 + p + 4]; al[mi][3] = Al[r8 + p + 4];
            }
#pragma unroll
            for (int ni = 0; ni < 4; ni++) {
                int nr = (wn + ni * 8 + gid) * SSTR;
                bh[ni][0] = Bh[nr + p]; bh[ni][1] = Bh[nr + p + 4];
                bl[ni][0] = Bl[nr + p]; bl[ni][1] = Bl[nr + p + 4];
            }
#pragma unroll
            for (int mi = 0; mi < 2; mi++)
#pragma unroll
                for (int ni = 0; ni < 4; ni++) {
                    mma_bf16(acc[mi][ni], ah[mi][0], ah[mi][1], ah[mi][2], ah[mi][3],
                             bh[ni][0], bh[ni][1]);
                    mma_bf16(acc[mi][ni], ah[mi][0], ah[mi][1], ah[mi][2], ah[mi][3],
                             bl[ni][0], bl[ni][1]);
                    mma_bf16(acc[mi][ni], al[mi][0], al[mi][1], al[mi][2], al[mi][3],
                             bh[ni][0], bh[ni][1]);
                }
        }
        __syncthreads();
    }
#pragma unroll
    for (int mi = 0; mi < 2; mi++) {
#pragma unroll
        for (int ni = 0; ni < 4; ni++) {
            int m = m0 + wm + mi * 16 + gid;
            int n = n0 + wn + ni * 8 + tig * 2;
            float b0v = bias[n], b1v = bias[n + 1];
            float* cp = C + (size_t)m * N + n;
            cp[0] = acc[mi][ni][0] + b0v; cp[1] = acc[mi][ni][1] + b1v;
            cp[(size_t)8 * N] = acc[mi][ni][2] + b0v;
            cp[(size_t)8 * N + 1] = acc[mi][ni][3] + b1v;
        }
    }
}

// ==========================================================================
// Expand scatter (fp16 temp -> fp32 out, + bev residual)
// ==========================================================================
__global__ void expand_scatter_k(const __half* __restrict__ T,
                                 const float* __restrict__ bev,
                                 float* __restrict__ out) {
    __shared__ float s[400][17];
    int bcg = blockIdx.x, py = blockIdx.y, bz = blockIdx.z;
    int b = bz / 20, hg = bz % 20;
    int tid = threadIdx.x;
    int mbase = b * LQ_ + hg * Wg_;
    const __half* tb = T + (size_t)mbase * NEXP_ + py * 2560 + bcg * 16;

#pragma unroll
    for (int it = 0; it < 25; it++) {
        int j = it * 256 + tid;
        int unit = j >> 4, bcl = j & 15;
        int wg = unit / 10, px = unit - wg * 10;
        s[unit][bcl] = __half2float(tb[(size_t)wg * NEXP_ + px * 256 + bcl]);
    }
    __syncthreads();

    int rowbase = hg * P_ + py;
#pragma unroll
    for (int it = 0; it < 25; it++) {
        int j = it * 256 + tid;
        int bcl = j / 400, pix = j - bcl * 400;
        int ch = bcg * 16 + bcl;
        size_t gi = (((size_t)b * BC_ + ch) * H_ + rowbase) * W_ + pix;
        out[gi] = s[pix][bcl] + bev[gi];
    }
}

// ==========================================================================
// LayerNorm family
// ==========================================================================
__device__ __forceinline__ float block_ln_val(float x, const float* __restrict__ g,
                                              const float* __restrict__ bt, int c) {
    __shared__ float red[2][8];
    float s = x, sq = x * x;
#pragma unroll
    for (int o = 16; o > 0; o >>= 1) {
        s  += __shfl_down_sync(0xffffffffu, s, o);
        sq += __shfl_down_sync(0xffffffffu, sq, o);
    }
    int w = c >> 5, lane = c & 31;
    if (lane == 0) { red[0][w] = s; red[1][w] = sq; }
    __syncthreads();
    float ts = 0.f, tq = 0.f;
#pragma unroll
    for (int i = 0; i < 8; i++) { ts += red[0][i]; tq += red[1][i]; }
    float mean = ts * (1.0f / HC_);
    float var  = tq * (1.0f / HC_) - mean * mean;
    float inv  = rsqrtf(var + 1e-5f);
    return (x - mean) * inv * g[c] + bt[c];
}

template<int SPLIT>
__global__ void add_pos_ln_red_k(const float* __restrict__ part,
                                 const float* __restrict__ cb,
                                 const float* __restrict__ pos,
                                 const float* __restrict__ g,
                                 const float* __restrict__ bt,
                                 float* __restrict__ Y) {
    int row = blockIdx.x, c = threadIdx.x;
    float x = 0.f;
#pragma unroll
    for (int z = 0; z < SPLIT; z++) x += part[(size_t)z * MT_ * HC_ + (size_t)row * HC_ + c];
    x += cb[c] + pos[(row % LQ_) * HC_ + c];
    Y[(size_t)row * HC_ + c] = block_ln_val(x, g, bt, c);
}

__global__ void ln_pair_k(const float* __restrict__ X,
                          const float* __restrict__ g,
                          const float* __restrict__ bt,
                          float* __restrict__ Y,
                          __nv_bfloat16* __restrict__ Ph,
                          __nv_bfloat16* __restrict__ Pl) {
    int row = blockIdx.x, c = threadIdx.x;
    float x = X[(size_t)row * HC_ + c];
    float v = block_ln_val(x, g, bt, c);
    size_t o = (size_t)row * HC_ + c;
    Y[o] = v;
    __nv_bfloat16 h, l; split1(v, h, l);
    Ph[o] = h; Pl[o] = l;
}

// ==========================================================================
// Deformable attention (writes fp32 + bf16 pair)
// ==========================================================================
__global__ void deform_k(const float* __restrict__ val,
                         const float* __restrict__ off,
                         const float* __restrict__ awl,
                         float* __restrict__ attn,
                         __nv_bfloat16* __restrict__ Ph,
                         __nv_bfloat16* __restrict__ Pl) {
    int row  = blockIdx.x;
    int h    = threadIdx.x >> 5;
    int lane = threadIdx.x & 31;
    int b = row / LQ_, l = row % LQ_;
    int hg = l / Wg_, wg = l % Wg_;

    float refx = ((float)wg + 0.5f) / (float)Wg_;
    float refy = ((float)hg + 0.5f) / (float)Hg_;

    float lg[NP_];
    float mx = -1e30f;
#pragma unroll
    for (int p = 0; p < NP_; p++) {
        lg[p] = awl[(size_t)row * (NH_ * NP_) + h * NP_ + p];
        mx = fmaxf(mx, lg[p]);
    }
    float den = 0.f;
#pragma unroll
    for (int p = 0; p < NP_; p++) { lg[p] = expf(lg[p] - mx); den += lg[p]; }
    float invden = 1.0f / den;

    const float* vb = val + (size_t)b * LQ_ * HC_ + h * DH_ + lane;
    float acc = 0.f;

#pragma unroll
    for (int p = 0; p < NP_; p++) {
        float ox = off[(size_t)row * (NH_ * NP_ * 2) + (h * NP_ + p) * 2 + 0];
        float oy = off[(size_t)row * (NH_ * NP_ * 2) + (h * NP_ + p) * 2 + 1];
        float x = (refx + ox * (1.0f / Wg_)) * (float)Wg_ - 0.5f;
        float y = (refy + oy * (1.0f / Hg_)) * (float)Hg_ - 0.5f;
        float xf = floorf(x), yf = floorf(y);
        int x0 = (int)xf, y0 = (int)yf;
        float lx = x - xf, ly = y - yf;
        float wp = lg[p] * invden;

        float w00 = (1.f - lx) * (1.f - ly);
        float w10 = lx * (1.f - ly);
        float w01 = (1.f - lx) * ly;
        float w11 = lx * ly;

        if (x0     >= 0 && x0     < Wg_ && y0     >= 0 && y0     < Hg_)
            acc = fmaf(wp * w00, vb[(size_t)(y0 * Wg_ + x0) * HC_], acc);
        if (x0 + 1 >= 0 && x0 + 1 < Wg_ && y0     >= 0 && y0     < Hg_)
            acc = fmaf(wp * w10, vb[(size_t)(y0 * Wg_ + x0 + 1) * HC_], acc);
        if (x0     >= 0 && x0     < Wg_ && y0 + 1 >= 0 && y0 + 1 < Hg_)
            acc = fmaf(wp * w01, vb[(size_t)((y0 + 1) * Wg_ + x0) * HC_], acc);
        if (x0 + 1 >= 0 && x0 + 1 < Wg_ && y0 + 1 >= 0 && y0 + 1 < Hg_)
            acc = fmaf(wp * w11, vb[(size_t)((y0 + 1) * Wg_ + x0 + 1) * HC_], acc);
    }
    size_t o = (size_t)row * HC_ + h * DH_ + lane;
    attn[o] = acc;
    __nv_bfloat16 hh, ll; split1(acc, hh, ll);
    Ph[o] = hh; Pl[o] = ll;
}

// ==========================================================================
// host launch
// ==========================================================================
extern "C" void kernel_launch(void* const* d_in, const int* in_sizes, int n_in,
                              void* d_out, int out_size) {
    const float* bev      = (const float*)d_in[0];
    const float* prior    = (const float*)d_in[1];
    const float* pe_bev_w = (const float*)d_in[2];
    const float* pe_bev_b = (const float*)d_in[3];
    const float* pe_pr_w  = (const float*)d_in[4];
    const float* pe_pr_b  = (const float*)d_in[5];
    const float* pos_bev  = (const float*)d_in[6];
    const float* pos_pr   = (const float*)d_in[7];
    const float* ln_bev_g = (const float*)d_in[8];
    const float* ln_bev_b = (const float*)d_in[9];
    const float* ln_pr_g  = (const float*)d_in[10];
    const float* ln_pr_b  = (const float*)d_in[11];
    const float* n1_g     = (const float*)d_in[12];
    const float* n1_b     = (const float*)d_in[13];
    const float* n2_g     = (const float*)d_in[14];
    const float* n2_b     = (const float*)d_in[15];
    const float* off_w    = (const float*)d_in[16];
    const float* off_b    = (const float*)d_in[17];
    const float* aw_w     = (const float*)d_in[18];
    const float* aw_b     = (const float*)d_in[19];
    const float* vp_w     = (const float*)d_in[20];
    const float* vp_b     = (const float*)d_in[21];
    const float* op_w     = (const float*)d_in[22];
    const float* op_b     = (const float*)d_in[23];
    const float* fc1_w    = (const float*)d_in[24];
    const float* fc1_b    = (const float*)d_in[25];
    const float* fc2_w    = (const float*)d_in[26];
    const float* fc2_b    = (const float*)d_in[27];
    const float* expand_w = (const float*)d_in[28];
    float* out = (float*)d_out;

    float *tgt, *pr, *t, *s, *val, *attn, *off, *aw, *part;
    __half *exph;
    __nv_bfloat16 *imh, *iml, *wh, *wl, *fc1h, *fc1l, *fc2h, *fc2l;
    __nv_bfloat16 *vph, *vpl, *oph, *opl, *ofh, *ofl;
    __nv_bfloat16 *th, *tl, *sh, *sl, *ath, *atl, *mlph, *mlpl, *tgh, *tgl;
    cudaGetSymbolAddress((void**)&tgt,  g_tgt);
    cudaGetSymbolAddress((void**)&pr,   g_pr);
    cudaGetSymbolAddress((void**)&t,    g_t);
    cudaGetSymbolAddress((void**)&s,    g_s);
    cudaGetSymbolAddress((void**)&val,  g_val);
    cudaGetSymbolAddress((void**)&attn, g_attn);
    cudaGetSymbolAddress((void**)&off,  g_off);
    cudaGetSymbolAddress((void**)&aw,   g_aw);
    cudaGetSymbolAddress((void**)&part, g_part);
    cudaGetSymbolAddress((void**)&exph, g_exph);
    cudaGetSymbolAddress((void**)&imh,  g_imh);
    cudaGetSymbolAddress((void**)&iml,  g_iml);
    cudaGetSymbolAddress((void**)&wh,   g_wh);
    cudaGetSymbolAddress((void**)&wl,   g_wl);
    cudaGetSymbolAddress((void**)&fc1h, g_fc1h);
    cudaGetSymbolAddress((void**)&fc1l, g_fc1l);
    cudaGetSymbolAddress((void**)&fc2h, g_fc2h);
    cudaGetSymbolAddress((void**)&fc2l, g_fc2l);
    cudaGetSymbolAddress((void**)&vph,  g_vph);
    cudaGetSymbolAddress((void**)&vpl,  g_vpl);
    cudaGetSymbolAddress((void**)&oph,  g_oph);
    cudaGetSymbolAddress((void**)&opl,  g_opl);
    cudaGetSymbolAddress((void**)&ofh,  g_ofh);
    cudaGetSymbolAddress((void**)&ofl,  g_ofl);
    cudaGetSymbolAddress((void**)&th,   g_th);
    cudaGetSymbolAddress((void**)&tl,   g_tl);
    cudaGetSymbolAddress((void**)&sh,   g_sh);
    cudaGetSymbolAddress((void**)&sl,   g_sl);
    cudaGetSymbolAddress((void**)&ath,  g_ath);
    cudaGetSymbolAddress((void**)&atl,  g_atl);
    cudaGetSymbolAddress((void**)&mlph, g_mlph);
    cudaGetSymbolAddress((void**)&mlpl, g_mlpl);
    cudaGetSymbolAddress((void**)&tgh,  g_tgh);
    cudaGetSymbolAddress((void**)&tgl,  g_tgl);

    cudaFuncSetAttribute(gbf_k<0u,4>, cudaFuncAttributeMaxDynamicSharedMemorySize, 2*GSTG);
    cudaFuncSetAttribute(gbf_k<FB_HALF,1>, cudaFuncAttributeMaxDynamicSharedMemorySize, 2*GSTG);
    cudaFuncSetAttribute(gbf_k<FB_BIAS|FB_F32,1>, cudaFuncAttributeMaxDynamicSharedMemorySize, 2*GSTG);
    cudaFuncSetAttribute(gbf_k<FB_BIAS|FB_GELU|FB_PAIR,1>, cudaFuncAttributeMaxDynamicSharedMemorySize, 2*GSTG);
    cudaFuncSetAttribute(gbf_k<FB_BIAS|FB_RES|FB_F32,1>, cudaFuncAttributeMaxDynamicSharedMemorySize, 2*GSTG);
    cudaFuncSetAttribute(gbf_k<FB_BIAS|FB_RES|FB_F32|FB_PAIR,1>, cudaFuncAttributeMaxDynamicSharedMemorySize, 2*GSTG);

    // ---- weight pair conversions (once) ----
    convert_pair_k<<<512, 256>>>(fc1_w, fc1h, fc1l, 2*MLPD_*HC_/4);
    convert_pair_k<<<512, 256>>>(fc2_w, fc2h, fc2l, 2*HC_*MLPD_/4);
    convert_pair_k<<<128, 256>>>(vp_w, vph, vpl, 2*HC_*HC_/4);
    convert_pair_k<<<128, 256>>>(op_w, oph, opl, 2*HC_*HC_/4);
    convert_pair_k<<<64, 256>>>(off_w, ofh, ofl, 2*128*HC_/4);

    // ---- bev patch-embed ----
    convert_pair_k<<<4096, 256>>>(pe_bev_w, wh, wl, HC_*KBEV_/4);
    im2col_pair_k<BC_><<<dim3(Hg_, BC_, B_), 256>>>(bev, imh, iml);
    gbf_k<0u,4><<<dim3(2, 25, 4), 256, 2*GSTG>>>(imh, iml, wh, wl, nullptr, nullptr,
                                                 part, nullptr, nullptr, nullptr, HC_, KBEV_);
    add_pos_ln_red_k<4><<<MT_, 256>>>(part, pe_bev_b, pos_bev, ln_bev_g, ln_bev_b, tgt);

    // ---- prior patch-embed ----
    convert_pair_k<<<1024, 256>>>(pe_pr_w, wh, wl, HC_*KPR_/4);
    im2col_pair_k<PC_><<<dim3(Hg_, PC_, B_), 256>>>(prior, imh, iml);
    gbf_k<0u,4><<<dim3(2, 25, 4), 256, 2*GSTG>>>(imh, iml, wh, wl, nullptr, nullptr,
                                                 part, nullptr, nullptr, nullptr, HC_, KPR_);
    add_pos_ln_red_k<4><<<MT_, 256>>>(part, pe_pr_b, pos_pr, ln_pr_g, ln_pr_b, pr);

    // ---- decoder layers ----
    for (int l = 0; l < 2; l++) {
        ln_pair_k<<<MT_, 256>>>(tgt, n1_g + l * HC_, n1_b + l * HC_, t, th, tl);
        ln_pair_k<<<MT_, 256>>>(pr,  n1_g + l * HC_, n1_b + l * HC_, s, sh, sl);

        gbf_k<FB_BIAS|FB_F32,1><<<dim3(2, 25), 256, 2*GSTG>>>(
            sh, sl, vph + l * HC_ * HC_, vpl + l * HC_ * HC_,
            vp_b + l * HC_, nullptr, val, nullptr, nullptr, nullptr, HC_, HC_);
        gbf_k<FB_BIAS|FB_F32,1><<<dim3(1, 25), 256, 2*GSTG>>>(
            th, tl, ofh + l * 128 * HC_, ofl + l * 128 * HC_,
            off_b + l * 128, nullptr, off, nullptr, nullptr, nullptr, 128, HC_);
        mma_gemm_aw_k<<<dim3(1, 50), 128>>>(t, aw_w + l * 64 * HC_, aw_b + l * 64,
                                            aw, 64, HC_);

        deform_k<<<MT_, 256>>>(val, off, aw, attn, ath, atl);

        gbf_k<FB_BIAS|FB_RES|FB_F32,1><<<dim3(2, 25), 256, 2*GSTG>>>(
            ath, atl, oph + l * HC_ * HC_, opl + l * HC_ * HC_,
            op_b + l * HC_, tgt, tgt, nullptr, nullptr, nullptr, HC_, HC_);

        ln_pair_k<<<MT_, 256>>>(tgt, n2_g + l * HC_, n2_b + l * HC_, t, th, tl);
        gbf_k<FB_BIAS|FB_GELU|FB_PAIR,1><<<dim3(8, 25), 256, 2*GSTG>>>(
            th, tl, fc1h + l * MLPD_ * HC_, fc1l + l * MLPD_ * HC_,
            fc1_b + l * MLPD_, nullptr, nullptr, nullptr, mlph, mlpl, MLPD_, HC_);
        gbf_k<FB_BIAS|FB_RES|FB_F32|FB_PAIR,1><<<dim3(2, 25), 256, 2*GSTG>>>(
            mlph, mlpl, fc2h + l * HC_ * MLPD_, fc2l + l * HC_ * MLPD_,
            fc2_b + l * HC_, tgt, tgt, nullptr, tgh, tgl, HC_, MLPD_);
    }

    // ---- expand ----
    convert_pair_k<<<4096, 256>>>(expand_w, wh, wl, NEXP_*HC_/4);
    gbf_k<FB_HALF,1><<<dim3(NEXP_/128, 25), 256, 2*GSTG>>>(
        tgh, tgl, wh, wl, nullptr, nullptr, nullptr, exph, nullptr, nullptr, NEXP_, HC_);
    expand_scatter_k<<<dim3(16, 10, 80), 256>>>(exph, bev, out);
}

// round 6
// speedup vs baseline: 1.0088x; 1.0088x over previous
#include <cuda_runtime.h>
#include <cuda_bf16.h>
#include <cuda_fp16.h>
#include <math.h>

// ---------------- static config ----------------
#define B_    4
#define BC_   256
#define PC_   64
#define HC_   256
#define H_    200
#define W_    400
#define P_    10
#define Hg_   20
#define Wg_   40
#define LQ_   800
#define MT_   (B_*LQ_)     // 3200 rows
#define NH_   8
#define NP_   8
#define DH_   32
#define MLPD_ 1024
#define NEXP_ 25600
#define KBEV_ 25600
#define KPR_  6400

// ---------------- scratch ----------------
__device__ float g_tgt [MT_*HC_];
__device__ float g_pr  [MT_*HC_];
__device__ float g_t   [MT_*HC_];
__device__ float g_s   [MT_*HC_];
__device__ float g_val [MT_*HC_];
__device__ float g_off [MT_*NH_*NP_*2];
__device__ float g_aw  [MT_*NH_*NP_];
__device__ float g_part[4*MT_*HC_];
__device__ __half g_exph[(size_t)MT_*NEXP_];    // fp16 expand temp

// bf16 hi/lo planes
__device__ __align__(256) __nv_bfloat16 g_imh [(size_t)MT_*KBEV_];
__device__ __align__(256) __nv_bfloat16 g_iml [(size_t)MT_*KBEV_];
__device__ __align__(256) __nv_bfloat16 g_wh  [6553600];
__device__ __align__(256) __nv_bfloat16 g_wl  [6553600];
__device__ __align__(256) __nv_bfloat16 g_fc1h[2*MLPD_*HC_];
__device__ __align__(256) __nv_bfloat16 g_fc1l[2*MLPD_*HC_];
__device__ __align__(256) __nv_bfloat16 g_fc2h[2*HC_*MLPD_];
__device__ __align__(256) __nv_bfloat16 g_fc2l[2*HC_*MLPD_];
__device__ __align__(256) __nv_bfloat16 g_oph [2*HC_*HC_];
__device__ __align__(256) __nv_bfloat16 g_opl [2*HC_*HC_];
__device__ __align__(256) __nv_bfloat16 g_th  [MT_*HC_];
__device__ __align__(256) __nv_bfloat16 g_tl  [MT_*HC_];
__device__ __align__(256) __nv_bfloat16 g_ath [MT_*HC_];
__device__ __align__(256) __nv_bfloat16 g_atl [MT_*HC_];
__device__ __align__(256) __nv_bfloat16 g_mlph[MT_*MLPD_];
__device__ __align__(256) __nv_bfloat16 g_mlpl[MT_*MLPD_];
__device__ __align__(256) __nv_bfloat16 g_tgh [MT_*HC_];
__device__ __align__(256) __nv_bfloat16 g_tgl [MT_*HC_];

// ---------------- helpers ----------------
__device__ __forceinline__ float gelu_exact(float x) {
    return 0.5f * x * (1.0f + erff(x * 0.70710678118654752f));
}
__device__ __forceinline__ void cvt_split2(float x, float y, unsigned &hi, unsigned &lo) {
    __nv_bfloat16 hx = __float2bfloat16(x);
    __nv_bfloat16 hy = __float2bfloat16(y);
    float rx = x - __bfloat162float(hx);
    float ry = y - __bfloat162float(hy);
    __nv_bfloat16 lx = __float2bfloat16(rx);
    __nv_bfloat16 ly = __float2bfloat16(ry);
    hi = ((unsigned)__bfloat16_as_ushort(hy) << 16) | (unsigned)__bfloat16_as_ushort(hx);
    lo = ((unsigned)__bfloat16_as_ushort(ly) << 16) | (unsigned)__bfloat16_as_ushort(lx);
}
__device__ __forceinline__ void split1(float v, __nv_bfloat16 &h, __nv_bfloat16 &l) {
    h = __float2bfloat16(v);
    l = __float2bfloat16(v - __bfloat162float(h));
}
__device__ __forceinline__ void mma_bf16(float* c,
                                         unsigned a0, unsigned a1, unsigned a2, unsigned a3,
                                         unsigned b0, unsigned b1) {
    asm volatile(
        "mma.sync.aligned.m16n8k16.row.col.f32.bf16.bf16.f32 "
        "{%0,%1,%2,%3}, {%4,%5,%6,%7}, {%8,%9}, {%0,%1,%2,%3};\n"
        : "+f"(c[0]), "+f"(c[1]), "+f"(c[2]), "+f"(c[3])
        : "r"(a0), "r"(a1), "r"(a2), "r"(a3), "r"(b0), "r"(b1));
}
__device__ __forceinline__ unsigned smem_u32(const void* p) {
    return (unsigned)__cvta_generic_to_shared(p);
}
__device__ __forceinline__ void cp16(unsigned s, const void* g) {
    asm volatile("cp.async.cg.shared.global [%0], [%1], 16;" :: "r"(s), "l"(g));
}
__device__ __forceinline__ void cp_commit() { asm volatile("cp.async.commit_group;"); }
template<int NN> __device__ __forceinline__ void cp_wait() {
    asm volatile("cp.async.wait_group %0;" :: "n"(NN));
}
__device__ __forceinline__ void ldsm4(unsigned &r0, unsigned &r1, unsigned &r2, unsigned &r3,
                                      unsigned addr) {
    asm volatile("ldmatrix.sync.aligned.m8n8.x4.shared.b16 {%0,%1,%2,%3}, [%4];"
                 : "=r"(r0), "=r"(r1), "=r"(r2), "=r"(r3) : "r"(addr));
}

// ==========================================================================
// fp32 -> bf16 hi/lo planes
// ==========================================================================
__global__ void convert_pair_k(const float* __restrict__ X,
                               __nv_bfloat16* __restrict__ Ph,
                               __nv_bfloat16* __restrict__ Pl, int n4) {
    for (int i = blockIdx.x * blockDim.x + threadIdx.x; i < n4; i += gridDim.x * blockDim.x) {
        float4 v = ((const float4*)X)[i];
        unsigned h0, l0, h1, l1;
        cvt_split2(v.x, v.y, h0, l0);
        cvt_split2(v.z, v.w, h1, l1);
        ((uint2*)Ph)[i] = make_uint2(h0, h1);
        ((uint2*)Pl)[i] = make_uint2(l0, l1);
    }
}

// ==========================================================================
// im2col + split to bf16 planes
// ==========================================================================
template<int CIN>
__global__ void im2col_pair_k(const float* __restrict__ X,
                              __nv_bfloat16* __restrict__ Ph,
                              __nv_bfloat16* __restrict__ Pl) {
    __shared__ float s[4000];
    int hg = blockIdx.x, ci = blockIdx.y, b = blockIdx.z;
    int tid = threadIdx.x;
    const int K = CIN * 100;
    const float* src = X + ((size_t)(b * CIN + ci) * H_ + hg * P_) * W_;
    for (int i = tid; i < 4000; i += 256) s[i] = src[i];
    __syncthreads();
    size_t rowbase = (size_t)(b * LQ_ + hg * Wg_);
    for (int j = tid; j < 4000; j += 256) {
        int wg = j / 100, idx = j - wg * 100;
        int py = idx / 10, px = idx - py * 10;
        float v = s[py * 400 + wg * 10 + px];
        __nv_bfloat16 h, l; split1(v, h, l);
        size_t o = (rowbase + wg) * K + ci * 100 + idx;
        Ph[o] = h; Pl[o] = l;
    }
}

// ==========================================================================
// Fast GEMM, 128x128x32, bf16 hi/lo planes, flag epilogue
// ==========================================================================
#define FB_BIAS 1u
#define FB_GELU 2u
#define FB_RES  4u
#define FB_PAIR 8u
#define FB_F32  16u
#define FB_HALF 32u
#define GSTG 40960

template<unsigned MODE, int SPLIT>
__global__ void __launch_bounds__(256) gbf_k(
        const __nv_bfloat16* __restrict__ Ah_g, const __nv_bfloat16* __restrict__ Al_g,
        const __nv_bfloat16* __restrict__ Bh_g, const __nv_bfloat16* __restrict__ Bl_g,
        const float* __restrict__ bias, const float* __restrict__ R,
        float* __restrict__ C, __half* __restrict__ Ch,
        __nv_bfloat16* __restrict__ Ph, __nv_bfloat16* __restrict__ Pl,
        int N, int K) {
    extern __shared__ char smraw[];
    unsigned sbase = smem_u32(smraw);

    int tid = threadIdx.x, warp = tid >> 5, lane = tid & 31;
    int m0 = blockIdx.y * 128, n0 = blockIdx.x * 128;
    int Kc = K / SPLIT;
    int kstart = (SPLIT > 1) ? blockIdx.z * Kc : 0;
    int nk = Kc / 32;
    int wm = (warp >> 2) * 64, wn = (warp & 3) * 32;
    int gid = lane >> 2, tig = lane & 3;

    float acc[4][4][4];
#pragma unroll
    for (int mi = 0; mi < 4; mi++)
#pragma unroll
        for (int ni = 0; ni < 4; ni++)
#pragma unroll
            for (int q = 0; q < 4; q++) acc[mi][ni][q] = 0.f;

    auto load_tile = [&](int kt, int st) {
        int kb = kstart + kt * 32;
        unsigned sb = sbase + st * GSTG;
#pragma unroll
        for (int j = 0; j < 2; j++) {
            int c = j * 256 + tid;
            int row = c >> 2, q = c & 3;
            unsigned so = row * 80 + q * 16;
            size_t ga = (size_t)(m0 + row) * K + kb + q * 8;
            size_t gb = (size_t)(n0 + row) * K + kb + q * 8;
            cp16(sb +         so, Ah_g + ga);
            cp16(sb + 10240 + so, Al_g + ga);
            cp16(sb + 20480 + so, Bh_g + gb);
            cp16(sb + 30720 + so, Bl_g + gb);
        }
    };

    auto compute = [&](int st) {
        unsigned sb = sbase + st * GSTG;
#pragma unroll
        for (int s = 0; s < 2; s++) {
            unsigned ah[4][4], al[4][4], bh[4][2], bl[4][2];
            int arow = wm + (lane & 15);
            unsigned abyte = ((lane >> 4) * 16) + s * 32;
#pragma unroll
            for (int mi = 0; mi < 4; mi++) {
                unsigned ad = sb + (arow + mi * 16) * 80 + abyte;
                ldsm4(ah[mi][0], ah[mi][1], ah[mi][2], ah[mi][3], ad);
                ldsm4(al[mi][0], al[mi][1], al[mi][2], al[mi][3], ad + 10240);
            }
            int q = lane >> 3, r = lane & 7;
            int brow = wn + ((q >> 1) << 3) + r;
            unsigned bbyte = (q & 1) * 16 + s * 32;
#pragma unroll
            for (int nj = 0; nj < 2; nj++) {
                unsigned bd = sb + 20480 + (brow + nj * 16) * 80 + bbyte;
                unsigned r0, r1, r2, r3;
                ldsm4(r0, r1, r2, r3, bd);
                bh[nj*2][0] = r0; bh[nj*2][1] = r1; bh[nj*2+1][0] = r2; bh[nj*2+1][1] = r3;
                ldsm4(r0, r1, r2, r3, bd + 10240);
                bl[nj*2][0] = r0; bl[nj*2][1] = r1; bl[nj*2+1][0] = r2; bl[nj*2+1][1] = r3;
            }
#pragma unroll
            for (int mi = 0; mi < 4; mi++)
#pragma unroll
                for (int ni = 0; ni < 4; ni++) {
                    mma_bf16(acc[mi][ni], ah[mi][0], ah[mi][1], ah[mi][2], ah[mi][3],
                             bh[ni][0], bh[ni][1]);
                    mma_bf16(acc[mi][ni], ah[mi][0], ah[mi][1], ah[mi][2], ah[mi][3],
                             bl[ni][0], bl[ni][1]);
                    mma_bf16(acc[mi][ni], al[mi][0], al[mi][1], al[mi][2], al[mi][3],
                             bh[ni][0], bh[ni][1]);
                }
        }
    };

    load_tile(0, 0);
    cp_commit();
    for (int kt = 0; kt < nk; kt++) {
        if (kt + 1 < nk) {
            load_tile(kt + 1, (kt + 1) & 1);
            cp_commit();
            cp_wait<1>();
        } else {
            cp_wait<0>();
        }
        __syncthreads();
        compute(kt & 1);
        __syncthreads();
    }

#pragma unroll
    for (int mi = 0; mi < 4; mi++) {
#pragma unroll
        for (int ni = 0; ni < 4; ni++) {
            int m = m0 + wm + mi * 16 + gid;
            int n = n0 + wn + ni * 8 + tig * 2;
            float v0 = acc[mi][ni][0], v1 = acc[mi][ni][1];
            float v2 = acc[mi][ni][2], v3 = acc[mi][ni][3];
            if (SPLIT > 1) {
                float* Cp = C + (size_t)blockIdx.z * ((size_t)MT_ * N);
                Cp[(size_t)m * N + n] = v0;       Cp[(size_t)m * N + n + 1] = v1;
                Cp[(size_t)(m + 8) * N + n] = v2; Cp[(size_t)(m + 8) * N + n + 1] = v3;
            } else {
                if (MODE & FB_BIAS) {
                    float b0 = bias[n], b1 = bias[n + 1];
                    v0 += b0; v1 += b1; v2 += b0; v3 += b1;
                }
                if (MODE & FB_RES) {
                    const float* rp = R + (size_t)m * N + n;
                    v0 += rp[0]; v1 += rp[1];
                    v2 += rp[(size_t)8 * N]; v3 += rp[(size_t)8 * N + 1];
                }
                if (MODE & FB_GELU) {
                    v0 = gelu_exact(v0); v1 = gelu_exact(v1);
                    v2 = gelu_exact(v2); v3 = gelu_exact(v3);
                }
                size_t o0 = (size_t)m * N + n, o1 = (size_t)(m + 8) * N + n;
                if (MODE & FB_F32) {
                    C[o0] = v0; C[o0 + 1] = v1; C[o1] = v2; C[o1 + 1] = v3;
                }
                if (MODE & FB_HALF) {
                    Ch[o0] = __float2half(v0); Ch[o0 + 1] = __float2half(v1);
                    Ch[o1] = __float2half(v2); Ch[o1 + 1] = __float2half(v3);
                }
                if (MODE & FB_PAIR) {
                    __nv_bfloat16 h, l;
                    split1(v0, h, l); Ph[o0] = h;     Pl[o0] = l;
                    split1(v1, h, l); Ph[o0 + 1] = h; Pl[o0 + 1] = l;
                    split1(v2, h, l); Ph[o1] = h;     Pl[o1] = l;
                    split1(v3, h, l); Ph[o1 + 1] = h; Pl[o1 + 1] = l;
                }
            }
        }
    }
}

// ==========================================================================
// Slow-path NT GEMM (fp32 in, inline split) for small decoder GEMMs
// ==========================================================================
#define SSTR 20
__global__ __launch_bounds__(128) void mma_gemm_k(
        const float* __restrict__ A, const float* __restrict__ Wt,
        const float* __restrict__ bias, float* __restrict__ C, int N, int K) {
    __shared__ unsigned Ah[64*SSTR], Al[64*SSTR], Bh[64*SSTR], Bl[64*SSTR];
    int tid  = threadIdx.x;
    int warp = tid >> 5, lane = tid & 31;
    int gid  = lane >> 2, tig = lane & 3;
    int m0 = blockIdx.y * 64, n0 = blockIdx.x * 64;
    int wm = (warp & 1) * 32, wn = (warp >> 1) * 32;

    int row = tid >> 1, half = tid & 1;
    const float* ap = A  + (size_t)(m0 + row) * K + half * 16;
    const float* bp = Wt + (size_t)(n0 + row) * K + half * 16;

    float4 fa[4], fb[4];
#pragma unroll
    for (int i = 0; i < 4; i++) {
        fa[i] = *(const float4*)(ap + i * 4);
        fb[i] = *(const float4*)(bp + i * 4);
    }
    float acc[2][4][4];
#pragma unroll
    for (int mi = 0; mi < 2; mi++)
#pragma unroll
        for (int ni = 0; ni < 4; ni++)
#pragma unroll
            for (int q = 0; q < 4; q++) acc[mi][ni][q] = 0.f;

    for (int k0 = 0; k0 < K; k0 += 32) {
        int sb = row * SSTR + half * 8;
#pragma unroll
        for (int i = 0; i < 4; i++) {
            unsigned h0, l0, h1, l1;
            cvt_split2(fa[i].x, fa[i].y, h0, l0);
            cvt_split2(fa[i].z, fa[i].w, h1, l1);
            Ah[sb + i*2] = h0; Ah[sb + i*2 + 1] = h1;
            Al[sb + i*2] = l0; Al[sb + i*2 + 1] = l1;
            cvt_split2(fb[i].x, fb[i].y, h0, l0);
            cvt_split2(fb[i].z, fb[i].w, h1, l1);
            Bh[sb + i*2] = h0; Bh[sb + i*2 + 1] = h1;
            Bl[sb + i*2] = l0; Bl[sb + i*2 + 1] = l1;
        }
        __syncthreads();
        if (k0 + 32 < K) {
#pragma unroll
            for (int i = 0; i < 4; i++) {
                fa[i] = *(const float4*)(ap + k0 + 32 + i * 4);
                fb[i] = *(const float4*)(bp + k0 + 32 + i * 4);
            }
        }
#pragma unroll
        for (int s = 0; s < 2; s++) {
            unsigned ah[2][4], al[2][4], bh[4][2], bl[4][2];
            int p = s * 8 + tig;
#pragma unroll
            for (int mi = 0; mi < 2; mi++) {
                int r0 = (wm + mi * 16 + gid) * SSTR;
                int r8 = r0 + 8 * SSTR;
                ah[mi][0] = Ah[r0 + p];     ah[mi][1] = Ah[r8 + p];
                ah[mi][2] = Ah[r0 + p + 4]; ah[mi][3] = Ah[r8 + p + 4];
                al[mi][0] = Al[r0 + p];     al[mi][1] = Al[r8 + p];
                al[mi][2] = Al[r0 + p + 4]; al[mi][3] = Al[r8 + p + 4];
            }
#pragma unroll
            for (int ni = 0; ni < 4; ni++) {
                int nr = (wn + ni * 8 + gid) * SSTR;
                bh[ni][0] = Bh[nr + p]; bh[ni][1] = Bh[nr + p + 4];
                bl[ni][0] = Bl[nr + p]; bl[ni][1] = Bl[nr + p + 4];
            }
#pragma unroll
            for (int mi = 0; mi < 2; mi++)
#pragma unroll
                for (int ni = 0; ni < 4; ni++) {
                    mma_bf16(acc[mi][ni], ah[mi][0], ah[mi][1], ah[mi][2], ah[mi][3],
                             bh[ni][0], bh[ni][1]);
                    mma_bf16(acc[mi][ni], ah[mi][0], ah[mi][1], ah[mi][2], ah[mi][3],
                             bl[ni][0], bl[ni][1]);
                    mma_bf16(acc[mi][ni], al[mi][0], al[mi][1], al[mi][2], al[mi][3],
                             bh[ni][0], bh[ni][1]);
                }
        }
        __syncthreads();
    }
#pragma unroll
    for (int mi = 0; mi < 2; mi++) {
#pragma unroll
        for (int ni = 0; ni < 4; ni++) {
            int m = m0 + wm + mi * 16 + gid;
            int n = n0 + wn + ni * 8 + tig * 2;
            float b0v = bias[n], b1v = bias[n + 1];
            float* cp = C + (size_t)m * N + n;
            cp[0] = acc[mi][ni][0] + b0v; cp[1] = acc[mi][ni][1] + b1v;
            cp[(size_t)8 * N] = acc[mi][ni][2] + b0v;
            cp[(size_t)8 * N + 1] = acc[mi][ni][3] + b1v;
        }
    }
}

// ==========================================================================
// Expand scatter (fp16 temp -> fp32 out, + bev residual)
// ==========================================================================
__global__ void expand_scatter_k(const __half* __restrict__ T,
                                 const float* __restrict__ bev,
                                 float* __restrict__ out) {
    __shared__ float s[400][17];
    int bcg = blockIdx.x, py = blockIdx.y, bz = blockIdx.z;
    int b = bz / 20, hg = bz % 20;
    int tid = threadIdx.x;
    int mbase = b * LQ_ + hg * Wg_;
    const __half* tb = T + (size_t)mbase * NEXP_ + py * 2560 + bcg * 16;

#pragma unroll
    for (int it = 0; it < 25; it++) {
        int j = it * 256 + tid;
        int unit = j >> 4, bcl = j & 15;
        int wg = unit / 10, px = unit - wg * 10;
        s[unit][bcl] = __half2float(tb[(size_t)wg * NEXP_ + px * 256 + bcl]);
    }
    __syncthreads();

    int rowbase = hg * P_ + py;
#pragma unroll
    for (int it = 0; it < 25; it++) {
        int j = it * 256 + tid;
        int bcl = j / 400, pix = j - bcl * 400;
        int ch = bcg * 16 + bcl;
        size_t gi = (((size_t)b * BC_ + ch) * H_ + rowbase) * W_ + pix;
        out[gi] = s[pix][bcl] + bev[gi];
    }
}

// ==========================================================================
// LayerNorm family
// ==========================================================================
__device__ __forceinline__ float block_ln_val(float x, const float* __restrict__ g,
                                              const float* __restrict__ bt, int c) {
    __shared__ float red[2][8];
    float s = x, sq = x * x;
#pragma unroll
    for (int o = 16; o > 0; o >>= 1) {
        s  += __shfl_down_sync(0xffffffffu, s, o);
        sq += __shfl_down_sync(0xffffffffu, sq, o);
    }
    int w = c >> 5, lane = c & 31;
    if (lane == 0) { red[0][w] = s; red[1][w] = sq; }
    __syncthreads();
    float ts = 0.f, tq = 0.f;
#pragma unroll
    for (int i = 0; i < 8; i++) { ts += red[0][i]; tq += red[1][i]; }
    float mean = ts * (1.0f / HC_);
    float var  = tq * (1.0f / HC_) - mean * mean;
    float inv  = rsqrtf(var + 1e-5f);
    return (x - mean) * inv * g[c] + bt[c];
}

template<int SPLIT>
__global__ void add_pos_ln_red_k(const float* __restrict__ part,
                                 const float* __restrict__ cb,
                                 const float* __restrict__ pos,
                                 const float* __restrict__ g,
                                 const float* __restrict__ bt,
                                 float* __restrict__ Y) {
    int row = blockIdx.x, c = threadIdx.x;
    float x = 0.f;
#pragma unroll
    for (int z = 0; z < SPLIT; z++) x += part[(size_t)z * MT_ * HC_ + (size_t)row * HC_ + c];
    x += cb[c] + pos[(row % LQ_) * HC_ + c];
    Y[(size_t)row * HC_ + c] = block_ln_val(x, g, bt, c);
}

__global__ void ln_k(const float* __restrict__ X,
                     const float* __restrict__ g,
                     const float* __restrict__ bt,
                     float* __restrict__ Y) {
    int row = blockIdx.x, c = threadIdx.x;
    float x = X[(size_t)row * HC_ + c];
    Y[(size_t)row * HC_ + c] = block_ln_val(x, g, bt, c);
}

// LN writing bf16 hi/lo pair (for fast-path fc1)
__global__ void ln_pair_k(const float* __restrict__ X,
                          const float* __restrict__ g,
                          const float* __restrict__ bt,
                          __nv_bfloat16* __restrict__ Ph,
                          __nv_bfloat16* __restrict__ Pl) {
    int row = blockIdx.x, c = threadIdx.x;
    float x = X[(size_t)row * HC_ + c];
    float v = block_ln_val(x, g, bt, c);
    size_t o = (size_t)row * HC_ + c;
    __nv_bfloat16 h, l; split1(v, h, l);
    Ph[o] = h; Pl[o] = l;
}

// ==========================================================================
// Deformable attention (writes bf16 pair only)
// ==========================================================================
__global__ void deform_k(const float* __restrict__ val,
                         const float* __restrict__ off,
                         const float* __restrict__ awl,
                         __nv_bfloat16* __restrict__ Ph,
                         __nv_bfloat16* __restrict__ Pl) {
    int row  = blockIdx.x;
    int h    = threadIdx.x >> 5;
    int lane = threadIdx.x & 31;
    int b = row / LQ_, l = row % LQ_;
    int hg = l / Wg_, wg = l % Wg_;

    float refx = ((float)wg + 0.5f) / (float)Wg_;
    float refy = ((float)hg + 0.5f) / (float)Hg_;

    float lg[NP_];
    float mx = -1e30f;
#pragma unroll
    for (int p = 0; p < NP_; p++) {
        lg[p] = awl[(size_t)row * (NH_ * NP_) + h * NP_ + p];
        mx = fmaxf(mx, lg[p]);
    }
    float den = 0.f;
#pragma unroll
    for (int p = 0; p < NP_; p++) { lg[p] = expf(lg[p] - mx); den += lg[p]; }
    float invden = 1.0f / den;

    const float* vb = val + (size_t)b * LQ_ * HC_ + h * DH_ + lane;
    float acc = 0.f;

#pragma unroll
    for (int p = 0; p < NP_; p++) {
        float ox = off[(size_t)row * (NH_ * NP_ * 2) + (h * NP_ + p) * 2 + 0];
        float oy = off[(size_t)row * (NH_ * NP_ * 2) + (h * NP_ + p) * 2 + 1];
        float x = (refx + ox * (1.0f / Wg_)) * (float)Wg_ - 0.5f;
        float y = (refy + oy * (1.0f / Hg_)) * (float)Hg_ - 0.5f;
        float xf = floorf(x), yf = floorf(y);
        int x0 = (int)xf, y0 = (int)yf;
        float lx = x - xf, ly = y - yf;
        float wp = lg[p] * invden;

        float w00 = (1.f - lx) * (1.f - ly);
        float w10 = lx * (1.f - ly);
        float w01 = (1.f - lx) * ly;
        float w11 = lx * ly;

        if (x0     >= 0 && x0     < Wg_ && y0     >= 0 && y0     < Hg_)
            acc = fmaf(wp * w00, vb[(size_t)(y0 * Wg_ + x0) * HC_], acc);
        if (x0 + 1 >= 0 && x0 + 1 < Wg_ && y0     >= 0 && y0     < Hg_)
            acc = fmaf(wp * w10, vb[(size_t)(y0 * Wg_ + x0 + 1) * HC_], acc);
        if (x0     >= 0 && x0     < Wg_ && y0 + 1 >= 0 && y0 + 1 < Hg_)
            acc = fmaf(wp * w01, vb[(size_t)((y0 + 1) * Wg_ + x0) * HC_], acc);
        if (x0 + 1 >= 0 && x0 + 1 < Wg_ && y0 + 1 >= 0 && y0 + 1 < Hg_)
            acc = fmaf(wp * w11, vb[(size_t)((y0 + 1) * Wg_ + x0 + 1) * HC_], acc);
    }
    size_t o = (size_t)row * HC_ + h * DH_ + lane;
    __nv_bfloat16 hh, ll; split1(acc, hh, ll);
    Ph[o] = hh; Pl[o] = ll;
}

// ==========================================================================
// host launch
// ==========================================================================
extern "C" void kernel_launch(void* const* d_in, const int* in_sizes, int n_in,
                              void* d_out, int out_size) {
    const float* bev      = (const float*)d_in[0];
    const float* prior    = (const float*)d_in[1];
    const float* pe_bev_w = (const float*)d_in[2];
    const float* pe_bev_b = (const float*)d_in[3];
    const float* pe_pr_w  = (const float*)d_in[4];
    const float* pe_pr_b  = (const float*)d_in[5];
    const float* pos_bev  = (const float*)d_in[6];
    const float* pos_pr   = (const float*)d_in[7];
    const float* ln_bev_g = (const float*)d_in[8];
    const float* ln_bev_b = (const float*)d_in[9];
    const float* ln_pr_g  = (const float*)d_in[10];
    const float* ln_pr_b  = (const float*)d_in[11];
    const float* n1_g     = (const float*)d_in[12];
    const float* n1_b     = (const float*)d_in[13];
    const float* n2_g     = (const float*)d_in[14];
    const float* n2_b     = (const float*)d_in[15];
    const float* off_w    = (const float*)d_in[16];
    const float* off_b    = (const float*)d_in[17];
    const float* aw_w     = (const float*)d_in[18];
    const float* aw_b     = (const float*)d_in[19];
    const float* vp_w     = (const float*)d_in[20];
    const float* vp_b     = (const float*)d_in[21];
    const float* op_w     = (const float*)d_in[22];
    const float* op_b     = (const float*)d_in[23];
    const float* fc1_w    = (const float*)d_in[24];
    const float* fc1_b    = (const float*)d_in[25];
    const float* fc2_w    = (const float*)d_in[26];
    const float* fc2_b    = (const float*)d_in[27];
    const float* expand_w = (const float*)d_in[28];
    float* out = (float*)d_out;

    float *tgt, *pr, *t, *s, *val, *off, *aw, *part;
    __half *exph;
    __nv_bfloat16 *imh, *iml, *wh, *wl, *fc1h, *fc1l, *fc2h, *fc2l, *oph, *opl;
    __nv_bfloat16 *th, *tl, *ath, *atl, *mlph, *mlpl, *tgh, *tgl;
    cudaGetSymbolAddress((void**)&tgt,  g_tgt);
    cudaGetSymbolAddress((void**)&pr,   g_pr);
    cudaGetSymbolAddress((void**)&t,    g_t);
    cudaGetSymbolAddress((void**)&s,    g_s);
    cudaGetSymbolAddress((void**)&val,  g_val);
    cudaGetSymbolAddress((void**)&off,  g_off);
    cudaGetSymbolAddress((void**)&aw,   g_aw);
    cudaGetSymbolAddress((void**)&part, g_part);
    cudaGetSymbolAddress((void**)&exph, g_exph);
    cudaGetSymbolAddress((void**)&imh,  g_imh);
    cudaGetSymbolAddress((void**)&iml,  g_iml);
    cudaGetSymbolAddress((void**)&wh,   g_wh);
    cudaGetSymbolAddress((void**)&wl,   g_wl);
    cudaGetSymbolAddress((void**)&fc1h, g_fc1h);
    cudaGetSymbolAddress((void**)&fc1l, g_fc1l);
    cudaGetSymbolAddress((void**)&fc2h, g_fc2h);
    cudaGetSymbolAddress((void**)&fc2l, g_fc2l);
    cudaGetSymbolAddress((void**)&oph,  g_oph);
    cudaGetSymbolAddress((void**)&opl,  g_opl);
    cudaGetSymbolAddress((void**)&th,   g_th);
    cudaGetSymbolAddress((void**)&tl,   g_tl);
    cudaGetSymbolAddress((void**)&ath,  g_ath);
    cudaGetSymbolAddress((void**)&atl,  g_atl);
    cudaGetSymbolAddress((void**)&mlph, g_mlph);
    cudaGetSymbolAddress((void**)&mlpl, g_mlpl);
    cudaGetSymbolAddress((void**)&tgh,  g_tgh);
    cudaGetSymbolAddress((void**)&tgl,  g_tgl);

    cudaFuncSetAttribute(gbf_k<0u,4>, cudaFuncAttributeMaxDynamicSharedMemorySize, 2*GSTG);
    cudaFuncSetAttribute(gbf_k<FB_HALF,1>, cudaFuncAttributeMaxDynamicSharedMemorySize, 2*GSTG);
    cudaFuncSetAttribute(gbf_k<FB_BIAS|FB_RES|FB_F32,1>, cudaFuncAttributeMaxDynamicSharedMemorySize, 2*GSTG);
    cudaFuncSetAttribute(gbf_k<FB_BIAS|FB_GELU|FB_PAIR,1>, cudaFuncAttributeMaxDynamicSharedMemorySize, 2*GSTG);
    cudaFuncSetAttribute(gbf_k<FB_BIAS|FB_RES|FB_F32|FB_PAIR,1>, cudaFuncAttributeMaxDynamicSharedMemorySize, 2*GSTG);

    // ---- once-off weight pair conversions for fast-path decoder GEMMs ----
    convert_pair_k<<<512, 256>>>(fc1_w, fc1h, fc1l, 2*MLPD_*HC_/4);
    convert_pair_k<<<512, 256>>>(fc2_w, fc2h, fc2l, 2*HC_*MLPD_/4);
    convert_pair_k<<<128, 256>>>(op_w, oph, opl, 2*HC_*HC_/4);

    // ---- bev patch-embed ----
    convert_pair_k<<<4096, 256>>>(pe_bev_w, wh, wl, HC_*KBEV_/4);
    im2col_pair_k<BC_><<<dim3(Hg_, BC_, B_), 256>>>(bev, imh, iml);
    gbf_k<0u,4><<<dim3(2, 25, 4), 256, 2*GSTG>>>(imh, iml, wh, wl, nullptr, nullptr,
                                                 part, nullptr, nullptr, nullptr, HC_, KBEV_);
    add_pos_ln_red_k<4><<<MT_, 256>>>(part, pe_bev_b, pos_bev, ln_bev_g, ln_bev_b, tgt);

    // ---- prior patch-embed ----
    convert_pair_k<<<1024, 256>>>(pe_pr_w, wh, wl, HC_*KPR_/4);
    im2col_pair_k<PC_><<<dim3(Hg_, PC_, B_), 256>>>(prior, imh, iml);
    gbf_k<0u,4><<<dim3(2, 25, 4), 256, 2*GSTG>>>(imh, iml, wh, wl, nullptr, nullptr,
                                                 part, nullptr, nullptr, nullptr, HC_, KPR_);
    add_pos_ln_red_k<4><<<MT_, 256>>>(part, pe_pr_b, pos_pr, ln_pr_g, ln_pr_b, pr);

    // ---- decoder layers ----
    for (int l = 0; l < 2; l++) {
        const float* n1g = n1_g + l * HC_;
        const float* n1b = n1_b + l * HC_;

        ln_k<<<MT_, 256>>>(tgt, n1g, n1b, t);
        ln_k<<<MT_, 256>>>(pr,  n1g, n1b, s);

        mma_gemm_k<<<dim3(4, 50), 128>>>(s, vp_w + l * HC_ * HC_, vp_b + l * HC_,
                                         val, HC_, HC_);
        mma_gemm_k<<<dim3(2, 50), 128>>>(t, off_w + l * 128 * HC_, off_b + l * 128,
                                         off, 128, HC_);
        mma_gemm_k<<<dim3(1, 50), 128>>>(t, aw_w + l * 64 * HC_, aw_b + l * 64,
                                         aw, 64, HC_);

        deform_k<<<MT_, 256>>>(val, off, aw, ath, atl);

        gbf_k<FB_BIAS|FB_RES|FB_F32,1><<<dim3(2, 25), 256, 2*GSTG>>>(
            ath, atl, oph + l * HC_ * HC_, opl + l * HC_ * HC_,
            op_b + l * HC_, tgt, tgt, nullptr, nullptr, nullptr, HC_, HC_);

        ln_pair_k<<<MT_, 256>>>(tgt, n2_g + l * HC_, n2_b + l * HC_, th, tl);
        gbf_k<FB_BIAS|FB_GELU|FB_PAIR,1><<<dim3(8, 25), 256, 2*GSTG>>>(
            th, tl, fc1h + l * MLPD_ * HC_, fc1l + l * MLPD_ * HC_,
            fc1_b + l * MLPD_, nullptr, nullptr, nullptr, mlph, mlpl, MLPD_, HC_);
        gbf_k<FB_BIAS|FB_RES|FB_F32|FB_PAIR,1><<<dim3(2, 25), 256, 2*GSTG>>>(
            mlph, mlpl, fc2h + l * HC_ * MLPD_, fc2l + l * HC_ * MLPD_,
            fc2_b + l * HC_, tgt, tgt, nullptr, tgh, tgl, HC_, MLPD_);
    }

    // ---- expand (tg pair emitted by layer-2 fc2 epilogue) ----
    convert_pair_k<<<4096, 256>>>(expand_w, wh, wl, NEXP_*HC_/4);
    gbf_k<FB_HALF,1><<<dim3(NEXP_/128, 25), 256, 2*GSTG>>>(
        tgh, tgl, wh, wl, nullptr, nullptr, nullptr, exph, nullptr, nullptr, NEXP_, HC_);
    expand_scatter_k<<<dim3(16, 10, 80), 256>>>(exph, bev, out);
}

// round 7
// speedup vs baseline: 1.1371x; 1.1271x over previous
#include <cuda_runtime.h>
#include <cuda_bf16.h>
#include <cuda_fp16.h>
#include <math.h>

// ---------------- static config ----------------
#define B_    4
#define BC_   256
#define PC_   64
#define HC_   256
#define H_    200
#define W_    400
#define P_    10
#define Hg_   20
#define Wg_   40
#define LQ_   800
#define MT_   (B_*LQ_)     // 3200 rows
#define NH_   8
#define NP_   8
#define DH_   32
#define MLPD_ 1024
#define NEXP_ 25600
#define KBEV_ 25600
#define KPR_  6400
#define NOA_  192          // concat off(128)+aw(64)

// ---------------- scratch ----------------
__device__ float g_tgt [MT_*HC_];
__device__ float g_pr  [MT_*HC_];
__device__ float g_t   [MT_*HC_];
__device__ float g_s   [MT_*HC_];
__device__ float g_val [MT_*HC_];
__device__ float g_attn[MT_*HC_];
__device__ float g_oa  [MT_*NOA_];
__device__ float g_mlp [MT_*MLPD_];
__device__ float g_part [4*MT_*HC_];
__device__ float g_part2[4*MT_*HC_];
__device__ float g_oaw [2*NOA_*HC_];
__device__ float g_oab [2*NOA_];
__device__ __half g_exph[(size_t)MT_*NEXP_];

// bf16 hi/lo planes
__device__ __align__(256) __nv_bfloat16 g_ibh [(size_t)MT_*KBEV_];
__device__ __align__(256) __nv_bfloat16 g_ibl [(size_t)MT_*KBEV_];
__device__ __align__(256) __nv_bfloat16 g_iph [(size_t)MT_*KPR_];
__device__ __align__(256) __nv_bfloat16 g_ipl [(size_t)MT_*KPR_];
__device__ __align__(256) __nv_bfloat16 g_wbh [HC_*KBEV_];
__device__ __align__(256) __nv_bfloat16 g_wbl [HC_*KBEV_];
__device__ __align__(256) __nv_bfloat16 g_wph [HC_*KPR_];
__device__ __align__(256) __nv_bfloat16 g_wpl [HC_*KPR_];
__device__ __align__(256) __nv_bfloat16 g_weh [NEXP_*HC_];
__device__ __align__(256) __nv_bfloat16 g_wel [NEXP_*HC_];
__device__ __align__(256) __nv_bfloat16 g_fc1h[2*MLPD_*HC_];
__device__ __align__(256) __nv_bfloat16 g_fc1l[2*MLPD_*HC_];
__device__ __align__(256) __nv_bfloat16 g_th  [MT_*HC_];
__device__ __align__(256) __nv_bfloat16 g_tl  [MT_*HC_];
__device__ __align__(256) __nv_bfloat16 g_tgh [MT_*HC_];
__device__ __align__(256) __nv_bfloat16 g_tgl [MT_*HC_];

// ---------------- helpers ----------------
__device__ __forceinline__ float gelu_exact(float x) {
    return 0.5f * x * (1.0f + erff(x * 0.70710678118654752f));
}
__device__ __forceinline__ void cvt_split2(float x, float y, unsigned &hi, unsigned &lo) {
    __nv_bfloat16 hx = __float2bfloat16(x);
    __nv_bfloat16 hy = __float2bfloat16(y);
    float rx = x - __bfloat162float(hx);
    float ry = y - __bfloat162float(hy);
    __nv_bfloat16 lx = __float2bfloat16(rx);
    __nv_bfloat16 ly = __float2bfloat16(ry);
    hi = ((unsigned)__bfloat16_as_ushort(hy) << 16) | (unsigned)__bfloat16_as_ushort(hx);
    lo = ((unsigned)__bfloat16_as_ushort(ly) << 16) | (unsigned)__bfloat16_as_ushort(lx);
}
__device__ __forceinline__ void split1(float v, __nv_bfloat16 &h, __nv_bfloat16 &l) {
    h = __float2bfloat16(v);
    l = __float2bfloat16(v - __bfloat162float(h));
}
__device__ __forceinline__ void mma_bf16(float* c,
                                         unsigned a0, unsigned a1, unsigned a2, unsigned a3,
                                         unsigned b0, unsigned b1) {
    asm volatile(
        "mma.sync.aligned.m16n8k16.row.col.f32.bf16.bf16.f32 "
        "{%0,%1,%2,%3}, {%4,%5,%6,%7}, {%8,%9}, {%0,%1,%2,%3};\n"
        : "+f"(c[0]), "+f"(c[1]), "+f"(c[2]), "+f"(c[3])
        : "r"(a0), "r"(a1), "r"(a2), "r"(a3), "r"(b0), "r"(b1));
}
__device__ __forceinline__ unsigned smem_u32(const void* p) {
    return (unsigned)__cvta_generic_to_shared(p);
}
__device__ __forceinline__ void cp16(unsigned s, const void* g) {
    asm volatile("cp.async.cg.shared.global [%0], [%1], 16;" :: "r"(s), "l"(g));
}
__device__ __forceinline__ void cp_commit() { asm volatile("cp.async.commit_group;"); }
template<int NN> __device__ __forceinline__ void cp_wait() {
    asm volatile("cp.async.wait_group %0;" :: "n"(NN));
}
__device__ __forceinline__ void ldsm4(unsigned &r0, unsigned &r1, unsigned &r2, unsigned &r3,
                                      unsigned addr) {
    asm volatile("ldmatrix.sync.aligned.m8n8.x4.shared.b16 {%0,%1,%2,%3}, [%4];"
                 : "=r"(r0), "=r"(r1), "=r"(r2), "=r"(r3) : "r"(addr));
}

// ==========================================================================
// fp32 -> bf16 hi/lo planes
// ==========================================================================
__global__ void convert_pair_k(const float* __restrict__ X,
                               __nv_bfloat16* __restrict__ Ph,
                               __nv_bfloat16* __restrict__ Pl, int n4) {
    for (int i = blockIdx.x * blockDim.x + threadIdx.x; i < n4; i += gridDim.x * blockDim.x) {
        float4 v = ((const float4*)X)[i];
        unsigned h0, l0, h1, l1;
        cvt_split2(v.x, v.y, h0, l0);
        cvt_split2(v.z, v.w, h1, l1);
        ((uint2*)Ph)[i] = make_uint2(h0, h1);
        ((uint2*)Pl)[i] = make_uint2(l0, l1);
    }
}

// concat off_w(128xHC) + aw_w(64xHC) -> 192xHC per layer, same for bias
__global__ void concat_ow_k(const float* __restrict__ off_w, const float* __restrict__ off_b,
                            const float* __restrict__ aw_w,  const float* __restrict__ aw_b,
                            float* __restrict__ Wc, float* __restrict__ Bc) {
    int n = blockIdx.x, l = blockIdx.y, c = threadIdx.x;
    const float* src = (n < 128) ? off_w + (size_t)(l * 128 + n) * HC_
                                 : aw_w  + (size_t)(l * 64 + (n - 128)) * HC_;
    Wc[(size_t)(l * NOA_ + n) * HC_ + c] = src[c];
    if (c == 0)
        Bc[l * NOA_ + n] = (n < 128) ? off_b[l * 128 + n] : aw_b[l * 64 + n - 128];
}

// ==========================================================================
// im2col + split to bf16 planes
// ==========================================================================
template<int CIN>
__global__ void im2col_pair_k(const float* __restrict__ X,
                              __nv_bfloat16* __restrict__ Ph,
                              __nv_bfloat16* __restrict__ Pl) {
    __shared__ float s[4000];
    int hg = blockIdx.x, ci = blockIdx.y, b = blockIdx.z;
    int tid = threadIdx.x;
    const int K = CIN * 100;
    const float* src = X + ((size_t)(b * CIN + ci) * H_ + hg * P_) * W_;
    for (int i = tid; i < 4000; i += 256) s[i] = src[i];
    __syncthreads();
    size_t rowbase = (size_t)(b * LQ_ + hg * Wg_);
    for (int j = tid; j < 4000; j += 256) {
        int wg = j / 100, idx = j - wg * 100;
        int py = idx / 10, px = idx - py * 10;
        float v = s[py * 400 + wg * 10 + px];
        __nv_bfloat16 h, l; split1(v, h, l);
        size_t o = (rowbase + wg) * K + ci * 100 + idx;
        Ph[o] = h; Pl[o] = l;
    }
}

// ==========================================================================
// Fast GEMM, 128x128x32, bf16 hi/lo planes, flag epilogue
// ==========================================================================
#define FB_BIAS 1u
#define FB_GELU 2u
#define FB_F32  4u
#define FB_HALF 8u
#define GSTG 40960

template<unsigned MODE, int SPLIT>
__global__ void __launch_bounds__(256) gbf_k(
        const __nv_bfloat16* __restrict__ Ah_g, const __nv_bfloat16* __restrict__ Al_g,
        const __nv_bfloat16* __restrict__ Bh_g, const __nv_bfloat16* __restrict__ Bl_g,
        const float* __restrict__ bias, float* __restrict__ C, __half* __restrict__ Ch,
        int N, int K) {
    extern __shared__ char smraw[];
    unsigned sbase = smem_u32(smraw);

    int tid = threadIdx.x, warp = tid >> 5, lane = tid & 31;
    int m0 = blockIdx.y * 128, n0 = blockIdx.x * 128;
    int Kc = K / SPLIT;
    int kstart = (SPLIT > 1) ? blockIdx.z * Kc : 0;
    int nk = Kc / 32;
    int wm = (warp >> 2) * 64, wn = (warp & 3) * 32;
    int gid = lane >> 2, tig = lane & 3;

    float acc[4][4][4];
#pragma unroll
    for (int mi = 0; mi < 4; mi++)
#pragma unroll
        for (int ni = 0; ni < 4; ni++)
#pragma unroll
            for (int q = 0; q < 4; q++) acc[mi][ni][q] = 0.f;

    auto load_tile = [&](int kt, int st) {
        int kb = kstart + kt * 32;
        unsigned sb = sbase + st * GSTG;
#pragma unroll
        for (int j = 0; j < 2; j++) {
            int c = j * 256 + tid;
            int row = c >> 2, q = c & 3;
            unsigned so = row * 80 + q * 16;
            size_t ga = (size_t)(m0 + row) * K + kb + q * 8;
            size_t gb = (size_t)(n0 + row) * K + kb + q * 8;
            cp16(sb +         so, Ah_g + ga);
            cp16(sb + 10240 + so, Al_g + ga);
            cp16(sb + 20480 + so, Bh_g + gb);
            cp16(sb + 30720 + so, Bl_g + gb);
        }
    };

    auto compute = [&](int st) {
        unsigned sb = sbase + st * GSTG;
#pragma unroll
        for (int s = 0; s < 2; s++) {
            unsigned ah[4][4], al[4][4], bh[4][2], bl[4][2];
            int arow = wm + (lane & 15);
            unsigned abyte = ((lane >> 4) * 16) + s * 32;
#pragma unroll
            for (int mi = 0; mi < 4; mi++) {
                unsigned ad = sb + (arow + mi * 16) * 80 + abyte;
                ldsm4(ah[mi][0], ah[mi][1], ah[mi][2], ah[mi][3], ad);
                ldsm4(al[mi][0], al[mi][1], al[mi][2], al[mi][3], ad + 10240);
            }
            int q = lane >> 3, r = lane & 7;
            int brow = wn + ((q >> 1) << 3) + r;
            unsigned bbyte = (q & 1) * 16 + s * 32;
#pragma unroll
            for (int nj = 0; nj < 2; nj++) {
                unsigned bd = sb + 20480 + (brow + nj * 16) * 80 + bbyte;
                unsigned r0, r1, r2, r3;
                ldsm4(r0, r1, r2, r3, bd);
                bh[nj*2][0] = r0; bh[nj*2][1] = r1; bh[nj*2+1][0] = r2; bh[nj*2+1][1] = r3;
                ldsm4(r0, r1, r2, r3, bd + 10240);
                bl[nj*2][0] = r0; bl[nj*2][1] = r1; bl[nj*2+1][0] = r2; bl[nj*2+1][1] = r3;
            }
#pragma unroll
            for (int mi = 0; mi < 4; mi++)
#pragma unroll
                for (int ni = 0; ni < 4; ni++) {
                    mma_bf16(acc[mi][ni], ah[mi][0], ah[mi][1], ah[mi][2], ah[mi][3],
                             bh[ni][0], bh[ni][1]);
                    mma_bf16(acc[mi][ni], ah[mi][0], ah[mi][1], ah[mi][2], ah[mi][3],
                             bl[ni][0], bl[ni][1]);
                    mma_bf16(acc[mi][ni], al[mi][0], al[mi][1], al[mi][2], al[mi][3],
                             bh[ni][0], bh[ni][1]);
                }
        }
    };

    load_tile(0, 0);
    cp_commit();
    for (int kt = 0; kt < nk; kt++) {
        if (kt + 1 < nk) {
            load_tile(kt + 1, (kt + 1) & 1);
            cp_commit();
            cp_wait<1>();
        } else {
            cp_wait<0>();
        }
        __syncthreads();
        compute(kt & 1);
        __syncthreads();
    }

#pragma unroll
    for (int mi = 0; mi < 4; mi++) {
#pragma unroll
        for (int ni = 0; ni < 4; ni++) {
            int m = m0 + wm + mi * 16 + gid;
            int n = n0 + wn + ni * 8 + tig * 2;
            float v0 = acc[mi][ni][0], v1 = acc[mi][ni][1];
            float v2 = acc[mi][ni][2], v3 = acc[mi][ni][3];
            if (SPLIT > 1) {
                float* Cp = C + (size_t)blockIdx.z * ((size_t)MT_ * N);
                Cp[(size_t)m * N + n] = v0;       Cp[(size_t)m * N + n + 1] = v1;
                Cp[(size_t)(m + 8) * N + n] = v2; Cp[(size_t)(m + 8) * N + n + 1] = v3;
            } else {
                if (MODE & FB_BIAS) {
                    float b0 = bias[n], b1 = bias[n + 1];
                    v0 += b0; v1 += b1; v2 += b0; v3 += b1;
                }
                if (MODE & FB_GELU) {
                    v0 = gelu_exact(v0); v1 = gelu_exact(v1);
                    v2 = gelu_exact(v2); v3 = gelu_exact(v3);
                }
                size_t o0 = (size_t)m * N + n, o1 = (size_t)(m + 8) * N + n;
                if (MODE & FB_F32) {
                    C[o0] = v0; C[o0 + 1] = v1; C[o1] = v2; C[o1 + 1] = v3;
                }
                if (MODE & FB_HALF) {
                    Ch[o0] = __float2half(v0); Ch[o0 + 1] = __float2half(v1);
                    Ch[o1] = __float2half(v2); Ch[o1 + 1] = __float2half(v3);
                }
            }
        }
    }
}

// ==========================================================================
// Slow-path NT GEMM (fp32 in, inline split) for small decoder GEMMs
// ==========================================================================
#define SSTR 20
template<int HAS_RES>
__global__ __launch_bounds__(128) void mma_gemm_k(
        const float* __restrict__ A, const float* __restrict__ Wt,
        const float* __restrict__ bias, const float* __restrict__ R,
        float* __restrict__ C, int N, int K) {
    __shared__ unsigned Ah[64*SSTR], Al[64*SSTR], Bh[64*SSTR], Bl[64*SSTR];
    int tid  = threadIdx.x;
    int warp = tid >> 5, lane = tid & 31;
    int gid  = lane >> 2, tig = lane & 3;
    int m0 = blockIdx.y * 64, n0 = blockIdx.x * 64;
    int wm = (warp & 1) * 32, wn = (warp >> 1) * 32;

    int row = tid >> 1, half = tid & 1;
    const float* ap = A  + (size_t)(m0 + row) * K + half * 16;
    const float* bp = Wt + (size_t)(n0 + row) * K + half * 16;

    float4 fa[4], fb[4];
#pragma unroll
    for (int i = 0; i < 4; i++) {
        fa[i] = *(const float4*)(ap + i * 4);
        fb[i] = *(const float4*)(bp + i * 4);
    }
    float acc[2][4][4];
#pragma unroll
    for (int mi = 0; mi < 2; mi++)
#pragma unroll
        for (int ni = 0; ni < 4; ni++)
#pragma unroll
            for (int q = 0; q < 4; q++) acc[mi][ni][q] = 0.f;

    for (int k0 = 0; k0 < K; k0 += 32) {
        int sb = row * SSTR + half * 8;
#pragma unroll
        for (int i = 0; i < 4; i++) {
            unsigned h0, l0, h1, l1;
            cvt_split2(fa[i].x, fa[i].y, h0, l0);
            cvt_split2(fa[i].z, fa[i].w, h1, l1);
            Ah[sb + i*2] = h0; Ah[sb + i*2 + 1] = h1;
            Al[sb + i*2] = l0; Al[sb + i*2 + 1] = l1;
            cvt_split2(fb[i].x, fb[i].y, h0, l0);
            cvt_split2(fb[i].z, fb[i].w, h1, l1);
            Bh[sb + i*2] = h0; Bh[sb + i*2 + 1] = h1;
            Bl[sb + i*2] = l0; Bl[sb + i*2 + 1] = l1;
        }
        __syncthreads();
        if (k0 + 32 < K) {
#pragma unroll
            for (int i = 0; i < 4; i++) {
                fa[i] = *(const float4*)(ap + k0 + 32 + i * 4);
                fb[i] = *(const float4*)(bp + k0 + 32 + i * 4);
            }
        }
#pragma unroll
        for (int s = 0; s < 2; s++) {
            unsigned ah[2][4], al[2][4], bh[4][2], bl[4][2];
            int p = s * 8 + tig;
#pragma unroll
            for (int mi = 0; mi < 2; mi++) {
                int r0 = (wm + mi * 16 + gid) * SSTR;
                int r8 = r0 + 8 * SSTR;
                ah[mi][0] = Ah[r0 + p];     ah[mi][1] = Ah[r8 + p];
                ah[mi][2] = Ah[r0 + p + 4]; ah[mi][3] = Ah[r8 + p + 4];
                al[mi][0] = Al[r0 + p];     al[mi][1] = Al[r8 + p];
                al[mi][2] = Al[r0 + p + 4]; al[mi][3] = Al[r8 + p + 4];
            }
#pragma unroll
            for (int ni = 0; ni < 4; ni++) {
                int nr = (wn + ni * 8 + gid) * SSTR;
                bh[ni][0] = Bh[nr + p]; bh[ni][1] = Bh[nr + p + 4];
                bl[ni][0] = Bl[nr + p]; bl[ni][1] = Bl[nr + p + 4];
            }
#pragma unroll
            for (int mi = 0; mi < 2; mi++)
#pragma unroll
                for (int ni = 0; ni < 4; ni++) {
                    mma_bf16(acc[mi][ni], ah[mi][0], ah[mi][1], ah[mi][2], ah[mi][3],
                             bh[ni][0], bh[ni][1]);
                    mma_bf16(acc[mi][ni], ah[mi][0], ah[mi][1], ah[mi][2], ah[mi][3],
                             bl[ni][0], bl[ni][1]);
                    mma_bf16(acc[mi][ni], al[mi][0], al[mi][1], al[mi][2], al[mi][3],
                             bh[ni][0], bh[ni][1]);
                }
        }
        __syncthreads();
    }
#pragma unroll
    for (int mi = 0; mi < 2; mi++) {
#pragma unroll
        for (int ni = 0; ni < 4; ni++) {
            int m = m0 + wm + mi * 16 + gid;
            int n = n0 + wn + ni * 8 + tig * 2;
            float b0v = bias[n], b1v = bias[n + 1];
            float v0 = acc[mi][ni][0] + b0v, v1 = acc[mi][ni][1] + b1v;
            float v2 = acc[mi][ni][2] + b0v, v3 = acc[mi][ni][3] + b1v;
            if (HAS_RES) {
                const float* rp = R + (size_t)m * N + n;
                v0 += rp[0]; v1 += rp[1];
                v2 += rp[(size_t)8 * N]; v3 += rp[(size_t)8 * N + 1];
            }
            float* cp = C + (size_t)m * N + n;
            cp[0] = v0; cp[1] = v1;
            cp[(size_t)8 * N] = v2; cp[(size_t)8 * N + 1] = v3;
        }
    }
}

// ==========================================================================
// Expand scatter (fp16 temp -> fp32 out, + bev residual)
// ==========================================================================
__global__ void expand_scatter_k(const __half* __restrict__ T,
                                 const float* __restrict__ bev,
                                 float* __restrict__ out) {
    __shared__ float s[400][17];
    int bcg = blockIdx.x, py = blockIdx.y, bz = blockIdx.z;
    int b = bz / 20, hg = bz % 20;
    int tid = threadIdx.x;
    int mbase = b * LQ_ + hg * Wg_;
    const __half* tb = T + (size_t)mbase * NEXP_ + py * 2560 + bcg * 16;

#pragma unroll
    for (int it = 0; it < 25; it++) {
        int j = it * 256 + tid;
        int unit = j >> 4, bcl = j & 15;
        int wg = unit / 10, px = unit - wg * 10;
        s[unit][bcl] = __half2float(tb[(size_t)wg * NEXP_ + px * 256 + bcl]);
    }
    __syncthreads();

    int rowbase = hg * P_ + py;
#pragma unroll
    for (int it = 0; it < 25; it++) {
        int j = it * 256 + tid;
        int bcl = j / 400, pix = j - bcl * 400;
        int ch = bcg * 16 + bcl;
        size_t gi = (((size_t)b * BC_ + ch) * H_ + rowbase) * W_ + pix;
        out[gi] = s[pix][bcl] + bev[gi];
    }
}

// ==========================================================================
// LayerNorm family
// ==========================================================================
__device__ __forceinline__ float block_ln_val(float x, const float* __restrict__ g,
                                              const float* __restrict__ bt, int c) {
    __shared__ float red[2][8];
    float s = x, sq = x * x;
#pragma unroll
    for (int o = 16; o > 0; o >>= 1) {
        s  += __shfl_down_sync(0xffffffffu, s, o);
        sq += __shfl_down_sync(0xffffffffu, sq, o);
    }
    int w = c >> 5, lane = c & 31;
    if (lane == 0) { red[0][w] = s; red[1][w] = sq; }
    __syncthreads();
    float ts = 0.f, tq = 0.f;
#pragma unroll
    for (int i = 0; i < 8; i++) { ts += red[0][i]; tq += red[1][i]; }
    float mean = ts * (1.0f / HC_);
    float var  = tq * (1.0f / HC_) - mean * mean;
    float inv  = rsqrtf(var + 1e-5f);
    return (x - mean) * inv * g[c] + bt[c];
}

template<int SPLIT>
__global__ void add_pos_ln_red_k(const float* __restrict__ part,
                                 const float* __restrict__ cb,
                                 const float* __restrict__ pos,
                                 const float* __restrict__ g,
                                 const float* __restrict__ bt,
                                 float* __restrict__ Y) {
    int row = blockIdx.x, c = threadIdx.x;
    float x = 0.f;
#pragma unroll
    for (int z = 0; z < SPLIT; z++) x += part[(size_t)z * MT_ * HC_ + (size_t)row * HC_ + c];
    x += cb[c] + pos[(row % LQ_) * HC_ + c];
    Y[(size_t)row * HC_ + c] = block_ln_val(x, g, bt, c);
}

// fused n1-LN of tgt->t and pr->s in one launch (blockIdx.y selects)
__global__ void ln2_k(const float* __restrict__ X0, float* __restrict__ Y0,
                      const float* __restrict__ X1, float* __restrict__ Y1,
                      const float* __restrict__ g, const float* __restrict__ bt) {
    int row = blockIdx.x, c = threadIdx.x;
    const float* X = blockIdx.y ? X1 : X0;
    float* Y = blockIdx.y ? Y1 : Y0;
    float x = X[(size_t)row * HC_ + c];
    Y[(size_t)row * HC_ + c] = block_ln_val(x, g, bt, c);
}

// LN writing bf16 hi/lo pair (for fast-path fc1)
__global__ void ln_pair_k(const float* __restrict__ X,
                          const float* __restrict__ g,
                          const float* __restrict__ bt,
                          __nv_bfloat16* __restrict__ Ph,
                          __nv_bfloat16* __restrict__ Pl) {
    int row = blockIdx.x, c = threadIdx.x;
    float x = X[(size_t)row * HC_ + c];
    float v = block_ln_val(x, g, bt, c);
    size_t o = (size_t)row * HC_ + c;
    __nv_bfloat16 h, l; split1(v, h, l);
    Ph[o] = h; Pl[o] = l;
}

// ==========================================================================
// Deformable attention (reads concat off|aw buffer, writes fp32 attn)
// ==========================================================================
__global__ void deform_k(const float* __restrict__ val,
                         const float* __restrict__ oa,
                         float* __restrict__ attn) {
    int row  = blockIdx.x;
    int h    = threadIdx.x >> 5;
    int lane = threadIdx.x & 31;
    int b = row / LQ_, l = row % LQ_;
    int hg = l / Wg_, wg = l % Wg_;

    float refx = ((float)wg + 0.5f) / (float)Wg_;
    float refy = ((float)hg + 0.5f) / (float)Hg_;

    const float* oarow = oa + (size_t)row * NOA_;
    float lg[NP_];
    float mx = -1e30f;
#pragma unroll
    for (int p = 0; p < NP_; p++) {
        lg[p] = oarow[128 + h * NP_ + p];
        mx = fmaxf(mx, lg[p]);
    }
    float den = 0.f;
#pragma unroll
    for (int p = 0; p < NP_; p++) { lg[p] = expf(lg[p] - mx); den += lg[p]; }
    float invden = 1.0f / den;

    const float* vb = val + (size_t)b * LQ_ * HC_ + h * DH_ + lane;
    float acc = 0.f;

#pragma unroll
    for (int p = 0; p < NP_; p++) {
        float ox = oarow[(h * NP_ + p) * 2 + 0];
        float oy = oarow[(h * NP_ + p) * 2 + 1];
        float x = (refx + ox * (1.0f / Wg_)) * (float)Wg_ - 0.5f;
        float y = (refy + oy * (1.0f / Hg_)) * (float)Hg_ - 0.5f;
        float xf = floorf(x), yf = floorf(y);
        int x0 = (int)xf, y0 = (int)yf;
        float lx = x - xf, ly = y - yf;
        float wp = lg[p] * invden;

        float w00 = (1.f - lx) * (1.f - ly);
        float w10 = lx * (1.f - ly);
        float w01 = (1.f - lx) * ly;
        float w11 = lx * ly;

        if (x0     >= 0 && x0     < Wg_ && y0     >= 0 && y0     < Hg_)
            acc = fmaf(wp * w00, vb[(size_t)(y0 * Wg_ + x0) * HC_], acc);
        if (x0 + 1 >= 0 && x0 + 1 < Wg_ && y0     >= 0 && y0     < Hg_)
            acc = fmaf(wp * w10, vb[(size_t)(y0 * Wg_ + x0 + 1) * HC_], acc);
        if (x0     >= 0 && x0     < Wg_ && y0 + 1 >= 0 && y0 + 1 < Hg_)
            acc = fmaf(wp * w01, vb[(size_t)((y0 + 1) * Wg_ + x0) * HC_], acc);
        if (x0 + 1 >= 0 && x0 + 1 < Wg_ && y0 + 1 >= 0 && y0 + 1 < Hg_)
            acc = fmaf(wp * w11, vb[(size_t)((y0 + 1) * Wg_ + x0 + 1) * HC_], acc);
    }
    attn[(size_t)row * HC_ + h * DH_ + lane] = acc;
}

// ==========================================================================
// host launch with multi-stream graph capture
// ==========================================================================
extern "C" void kernel_launch(void* const* d_in, const int* in_sizes, int n_in,
                              void* d_out, int out_size) {
    const float* bev      = (const float*)d_in[0];
    const float* prior    = (const float*)d_in[1];
    const float* pe_bev_w = (const float*)d_in[2];
    const float* pe_bev_b = (const float*)d_in[3];
    const float* pe_pr_w  = (const float*)d_in[4];
    const float* pe_pr_b  = (const float*)d_in[5];
    const float* pos_bev  = (const float*)d_in[6];
    const float* pos_pr   = (const float*)d_in[7];
    const float* ln_bev_g = (const float*)d_in[8];
    const float* ln_bev_b = (const float*)d_in[9];
    const float* ln_pr_g  = (const float*)d_in[10];
    const float* ln_pr_b  = (const float*)d_in[11];
    const float* n1_g     = (const float*)d_in[12];
    const float* n1_b     = (const float*)d_in[13];
    const float* n2_g     = (const float*)d_in[14];
    const float* n2_b     = (const float*)d_in[15];
    const float* off_w    = (const float*)d_in[16];
    const float* off_b    = (const float*)d_in[17];
    const float* aw_w     = (const float*)d_in[18];
    const float* aw_b     = (const float*)d_in[19];
    const float* vp_w     = (const float*)d_in[20];
    const float* vp_b     = (const float*)d_in[21];
    const float* op_w     = (const float*)d_in[22];
    const float* op_b     = (const float*)d_in[23];
    const float* fc1_w    = (const float*)d_in[24];
    const float* fc1_b    = (const float*)d_in[25];
    const float* fc2_w    = (const float*)d_in[26];
    const float* fc2_b    = (const float*)d_in[27];
    const float* expand_w = (const float*)d_in[28];
    float* out = (float*)d_out;

    float *tgt, *pr, *t, *s, *val, *attn, *oa, *mlp, *part, *part2, *oaw, *oab;
    __half *exph;
    __nv_bfloat16 *ibh, *ibl, *iph, *ipl, *wbh, *wbl, *wph, *wpl, *weh, *wel;
    __nv_bfloat16 *fc1h, *fc1l, *th, *tl, *tgh, *tgl;
    cudaGetSymbolAddress((void**)&tgt,  g_tgt);
    cudaGetSymbolAddress((void**)&pr,   g_pr);
    cudaGetSymbolAddress((void**)&t,    g_t);
    cudaGetSymbolAddress((void**)&s,    g_s);
    cudaGetSymbolAddress((void**)&val,  g_val);
    cudaGetSymbolAddress((void**)&attn, g_attn);
    cudaGetSymbolAddress((void**)&oa,   g_oa);
    cudaGetSymbolAddress((void**)&mlp,  g_mlp);
    cudaGetSymbolAddress((void**)&part, g_part);
    cudaGetSymbolAddress((void**)&part2,g_part2);
    cudaGetSymbolAddress((void**)&oaw,  g_oaw);
    cudaGetSymbolAddress((void**)&oab,  g_oab);
    cudaGetSymbolAddress((void**)&exph, g_exph);
    cudaGetSymbolAddress((void**)&ibh,  g_ibh);
    cudaGetSymbolAddress((void**)&ibl,  g_ibl);
    cudaGetSymbolAddress((void**)&iph,  g_iph);
    cudaGetSymbolAddress((void**)&ipl,  g_ipl);
    cudaGetSymbolAddress((void**)&wbh,  g_wbh);
    cudaGetSymbolAddress((void**)&wbl,  g_wbl);
    cudaGetSymbolAddress((void**)&wph,  g_wph);
    cudaGetSymbolAddress((void**)&wpl,  g_wpl);
    cudaGetSymbolAddress((void**)&weh,  g_weh);
    cudaGetSymbolAddress((void**)&wel,  g_wel);
    cudaGetSymbolAddress((void**)&fc1h, g_fc1h);
    cudaGetSymbolAddress((void**)&fc1l, g_fc1l);
    cudaGetSymbolAddress((void**)&th,   g_th);
    cudaGetSymbolAddress((void**)&tl,   g_tl);
    cudaGetSymbolAddress((void**)&tgh,  g_tgh);
    cudaGetSymbolAddress((void**)&tgl,  g_tgl);

    cudaFuncSetAttribute(gbf_k<0u,4>, cudaFuncAttributeMaxDynamicSharedMemorySize, 2*GSTG);
    cudaFuncSetAttribute(gbf_k<FB_HALF,1>, cudaFuncAttributeMaxDynamicSharedMemorySize, 2*GSTG);
    cudaFuncSetAttribute(gbf_k<FB_BIAS|FB_GELU|FB_F32,1>, cudaFuncAttributeMaxDynamicSharedMemorySize, 2*GSTG);

    // streams/events created once (resource handles only; identical work each call)
    static cudaStream_t s1 = nullptr, s2 = nullptr;
    static cudaEvent_t ev[16];
    if (!s1) {
        cudaStreamCreateWithFlags(&s1, cudaStreamNonBlocking);
        cudaStreamCreateWithFlags(&s2, cudaStreamNonBlocking);
        for (int i = 0; i < 16; i++) cudaEventCreateWithFlags(&ev[i], cudaEventDisableTiming);
    }

    // ---- fork ----
    cudaEventRecord(ev[0], 0);
    cudaStreamWaitEvent(s1, ev[0], 0);
    cudaStreamWaitEvent(s2, ev[0], 0);

    // s1: bev patch-embed chain
    convert_pair_k<<<4096, 256, 0, s1>>>(pe_bev_w, wbh, wbl, HC_*KBEV_/4);
    im2col_pair_k<BC_><<<dim3(Hg_, BC_, B_), 256, 0, s1>>>(bev, ibh, ibl);
    gbf_k<0u,4><<<dim3(2, 25, 4), 256, 2*GSTG, s1>>>(ibh, ibl, wbh, wbl, nullptr,
                                                     part, nullptr, HC_, KBEV_);
    add_pos_ln_red_k<4><<<MT_, 256, 0, s1>>>(part, pe_bev_b, pos_bev, ln_bev_g, ln_bev_b, tgt);
    cudaEventRecord(ev[1], s1);

    // s2: prior patch-embed chain
    convert_pair_k<<<1024, 256, 0, s2>>>(pe_pr_w, wph, wpl, HC_*KPR_/4);
    im2col_pair_k<PC_><<<dim3(Hg_, PC_, B_), 256, 0, s2>>>(prior, iph, ipl);
    gbf_k<0u,4><<<dim3(2, 25, 4), 256, 2*GSTG, s2>>>(iph, ipl, wph, wpl, nullptr,
                                                     part2, nullptr, HC_, KPR_);
    add_pos_ln_red_k<4><<<MT_, 256, 0, s2>>>(part2, pe_pr_b, pos_pr, ln_pr_g, ln_pr_b, pr);
    cudaEventRecord(ev[2], s2);

    // s0: independent weight prep (overlaps both chains)
    convert_pair_k<<<512, 256>>>(fc1_w, fc1h, fc1l, 2*MLPD_*HC_/4);
    convert_pair_k<<<4096, 256>>>(expand_w, weh, wel, NEXP_*HC_/4);
    concat_ow_k<<<dim3(NOA_, 2), 256>>>(off_w, off_b, aw_w, aw_b, oaw, oab);

    // join
    cudaStreamWaitEvent(0, ev[1], 0);
    cudaStreamWaitEvent(0, ev[2], 0);

    // ---- decoder layers ----
    for (int l = 0; l < 2; l++) {
        int eb = 4 + l * 4;
        ln2_k<<<dim3(MT_, 2), 256>>>(tgt, t, pr, s, n1_g + l * HC_, n1_b + l * HC_);

        // fork: vp on s1, off+aw on s0
        cudaEventRecord(ev[eb], 0);
        cudaStreamWaitEvent(s1, ev[eb], 0);
        mma_gemm_k<0><<<dim3(4, 50), 128, 0, s1>>>(s, vp_w + l * HC_ * HC_, vp_b + l * HC_,
                                                   nullptr, val, HC_, HC_);
        cudaEventRecord(ev[eb + 1], s1);
        mma_gemm_k<0><<<dim3(3, 50), 128>>>(t, oaw + l * NOA_ * HC_, oab + l * NOA_,
                                            nullptr, oa, NOA_, HC_);
        cudaStreamWaitEvent(0, ev[eb + 1], 0);

        deform_k<<<MT_, 256>>>(val, oa, attn);

        mma_gemm_k<1><<<dim3(4, 50), 128>>>(attn, op_w + l * HC_ * HC_, op_b + l * HC_,
                                            tgt, tgt, HC_, HC_);

        ln_pair_k<<<MT_, 256>>>(tgt, n2_g + l * HC_, n2_b + l * HC_, th, tl);
        gbf_k<FB_BIAS|FB_GELU|FB_F32,1><<<dim3(8, 25), 256, 2*GSTG>>>(
            th, tl, fc1h + l * MLPD_ * HC_, fc1l + l * MLPD_ * HC_,
            fc1_b + l * MLPD_, mlp, nullptr, MLPD_, HC_);
        mma_gemm_k<1><<<dim3(4, 50), 128>>>(mlp, fc2_w + l * HC_ * MLPD_, fc2_b + l * HC_,
                                            tgt, tgt, HC_, MLPD_);
    }

    // ---- expand ----
    convert_pair_k<<<800, 256>>>(tgt, tgh, tgl, MT_*HC_/4);
    gbf_k<FB_HALF,1><<<dim3(NEXP_/128, 25), 256, 2*GSTG>>>(
        tgh, tgl, weh, wel, nullptr, nullptr, exph, NEXP_, HC_);
    expand_scatter_k<<<dim3(16, 10, 80), 256>>>(exph, bev, out);
}